// round 11
// baseline (speedup 1.0000x reference)
#include <cuda_runtime.h>
#include <cuda_bf16.h>
#include <mma.h>
#include <cstdint>

using namespace nvcuda;

#define B_TOT 32768
#define T_LEN 200
#define DE    6
#define NIV   8
#define H     128
#define DIN   46
#define TD    (T_LEN*DE)
#define MROWS 128
#define NCTA  (B_TOT/MROWS)

// ---- bf16-element offsets in dynamic smem ----
#define O_WE_H 0
#define O_WE_L (O_WE_H + H*32)
#define O_WD_H (O_WE_L + H*32)
#define O_WD_L (O_WD_H + H*32)
#define O_VE_H (O_WD_L + H*32)
#define O_VE_L (O_VE_H + 16*H)
#define O_VD_H (O_VE_L + 16*H)
#define O_VD_L (O_VD_H + 16*H)
#define O_X_H  (O_VD_L + 16*H)
#define O_X_L  (O_X_H + MROWS*32)
#define O_R_H  (O_X_L + MROWS*32)
#define O_R_L  (O_R_H + MROWS*H)
#define NBF    (O_R_L + MROWS*H)
#define SMEM_TOTAL (NBF*2 + MROWS*16*4)   // bf16 region + fp32 staging

typedef wmma::fragment<wmma::matrix_a, 16,16,16, __nv_bfloat16, wmma::row_major> FragA;
typedef wmma::fragment<wmma::matrix_b, 16,16,16, __nv_bfloat16, wmma::col_major> FragB;
typedef wmma::fragment<wmma::accumulator, 16,16,16, float> FragC;

static __device__ __forceinline__ void split_st(__nv_bfloat16* hb, __nv_bfloat16* lb, float f) {
    __nv_bfloat16 h = __float2bfloat16(f);
    *hb = h;
    *lb = __float2bfloat16(f - __bfloat162float(h));
}

// One MLP pass for this warp's 32 rows: GEMM1 (X@W^T, relu, split->R) then
// GEMM2 (R@V^T -> sS). All smem rows touched belong to this warp.
static __device__ __forceinline__ void mlp_pass(
    __nv_bfloat16* sb, float* sS, int warp, int lane,
    int oWh, int oWl, int oVh, int oVl)
{
    const int rb = warp * 32;
    __nv_bfloat16* Xh = sb + O_X_H;
    __nv_bfloat16* Xl = sb + O_X_L;
    __nv_bfloat16* Rh = sb + O_R_H;
    __nv_bfloat16* Rl = sb + O_R_L;
    const __nv_bfloat16* Wh = sb + oWh;
    const __nv_bfloat16* Wl = sb + oWl;
    const __nv_bfloat16* Vh = sb + oVh;
    const __nv_bfloat16* Vl = sb + oVl;

    // A fragments (X rows of this warp), hoisted across all n-tiles
    FragA aH[2][2], aL[2][2];
#pragma unroll
    for (int mt = 0; mt < 2; ++mt)
#pragma unroll
        for (int k = 0; k < 2; ++k) {
            wmma::load_matrix_sync(aH[mt][k], Xh + (rb + mt*16)*32 + k*16, 32);
            wmma::load_matrix_sync(aL[mt][k], Xl + (rb + mt*16)*32 + k*16, 32);
        }

    // GEMM1: P[32,128] = X @ W^T, split passes hh + hl + lh; relu; split->R
#pragma unroll
    for (int nt = 0; nt < 8; ++nt) {
        FragB bH[2], bL[2];
#pragma unroll
        for (int k = 0; k < 2; ++k) {
            wmma::load_matrix_sync(bH[k], Wh + (nt*16)*32 + k*16, 32);
            wmma::load_matrix_sync(bL[k], Wl + (nt*16)*32 + k*16, 32);
        }
#pragma unroll
        for (int mt = 0; mt < 2; ++mt) {
            FragC acc;
            wmma::fill_fragment(acc, 0.0f);
#pragma unroll
            for (int k = 0; k < 2; ++k) wmma::mma_sync(acc, aH[mt][k], bH[k], acc);
#pragma unroll
            for (int k = 0; k < 2; ++k) wmma::mma_sync(acc, aH[mt][k], bL[k], acc);
#pragma unroll
            for (int k = 0; k < 2; ++k) wmma::mma_sync(acc, aL[mt][k], bH[k], acc);
#pragma unroll
            for (int i = 0; i < acc.num_elements; ++i) acc.x[i] = fmaxf(acc.x[i], 0.0f);

            wmma::store_matrix_sync(sS + (rb + mt*16)*16, acc, 16, wmma::mem_row_major);
            __syncwarp();
            // convert staged fp32 tile -> bf16 hi/lo in R (lane owns 8 contiguous cols of one row)
            int r  = rb + mt*16 + (lane >> 1);
            int cb = (lane & 1) * 8;
            const float* src = sS + r*16 + cb;
            __nv_bfloat16* dh = Rh + r*H + nt*16 + cb;
            __nv_bfloat16* dl = Rl + r*H + nt*16 + cb;
#pragma unroll
            for (int i = 0; i < 8; ++i) split_st(dh + i, dl + i, src[i]);
            __syncwarp();
        }
    }

    // GEMM2: ge[32,16] = R @ V^T (K=128), split hh + hl + lh
#pragma unroll
    for (int mt = 0; mt < 2; ++mt) {
        FragC acc;
        wmma::fill_fragment(acc, 0.0f);
#pragma unroll
        for (int k = 0; k < 8; ++k) {
            FragA ah, al;
            FragB bh, bl;
            wmma::load_matrix_sync(ah, Rh + (rb + mt*16)*H + k*16, H);
            wmma::load_matrix_sync(al, Rl + (rb + mt*16)*H + k*16, H);
            wmma::load_matrix_sync(bh, Vh + k*16, H);
            wmma::load_matrix_sync(bl, Vl + k*16, H);
            wmma::mma_sync(acc, ah, bh, acc);
            wmma::mma_sync(acc, ah, bl, acc);
            wmma::mma_sync(acc, al, bh, acc);
        }
        wmma::store_matrix_sync(sS + (rb + mt*16)*16, acc, 16, wmma::mem_row_major);
    }
    __syncwarp();
}

__global__ void __launch_bounds__(128, 1) visco_wmma(
    const float* __restrict__ e,   const float* __restrict__ edot,
    const float* __restrict__ Eg,  const float* __restrict__ nug,
    const float* __restrict__ We1, const float* __restrict__ be1,
    const float* __restrict__ We2,
    const float* __restrict__ Wd1, const float* __restrict__ bd1,
    const float* __restrict__ Wd2,
    const float* __restrict__ WE,  const float* __restrict__ bE,
    const float* __restrict__ Wnu, const float* __restrict__ bnu,
    float* __restrict__ out)
{
    extern __shared__ __align__(128) char smem[];
    __nv_bfloat16* sb = (__nv_bfloat16*)smem;
    float* sS = (float*)(smem + (size_t)NBF * 2);

    const int tid = threadIdx.x, warp = tid >> 5, lane = tid & 31;

    // zero everything (padding columns/rows must be 0)
    for (int i = tid; i < SMEM_TOTAL / 4; i += 128) ((uint32_t*)smem)[i] = 0;
    __syncthreads();

    // ---- derived weight tiles (thread h = tid) ----
    {
        const int h = tid;
        const float* w1 = We1 + h * DIN;
        float aE = be1[h], btE = 0.f, gmE = 0.f;
#pragma unroll
        for (int k = 0; k < 16; ++k) { float w = w1[14 + k]; aE += w * bE[k];  btE += w * WE[k]; }
#pragma unroll
        for (int k = 0; k < 16; ++k) { float w = w1[30 + k]; aE += w * bnu[k]; gmE += w * Wnu[k]; }
#pragma unroll
        for (int j = 0; j < 14; ++j)
            split_st(sb + O_WE_H + h*32 + j, sb + O_WE_L + h*32 + j, w1[j]);
        split_st(sb + O_WE_H + h*32 + 14, sb + O_WE_L + h*32 + 14, aE);
        split_st(sb + O_WE_H + h*32 + 15, sb + O_WE_L + h*32 + 15, btE);
        split_st(sb + O_WE_H + h*32 + 16, sb + O_WE_L + h*32 + 16, gmE);

        const float* w2 = Wd1 + h * DIN;
        float aD = bd1[h], btD = 0.f, gmD = 0.f;
#pragma unroll
        for (int k = 0; k < 16; ++k) { float w = w2[14 + k]; aD += w * bE[k];  btD += w * WE[k]; }
#pragma unroll
        for (int k = 0; k < 16; ++k) { float w = w2[30 + k]; aD += w * bnu[k]; gmD += w * Wnu[k]; }
#pragma unroll
        for (int j = 0; j < 14; ++j)
            split_st(sb + O_WD_H + h*32 + j, sb + O_WD_L + h*32 + j, w2[j]);
        split_st(sb + O_WD_H + h*32 + 14, sb + O_WD_L + h*32 + 14, aD);
        split_st(sb + O_WD_H + h*32 + 15, sb + O_WD_L + h*32 + 15, btD);
        split_st(sb + O_WD_H + h*32 + 16, sb + O_WD_L + h*32 + 16, gmD);

        // V[j][h] = 2 * c_h * W1[h][j]
        const float cE = 2.f * (We2[h] + We2[H + h]);
        const float cD = 2.f * Wd2[h];
#pragma unroll
        for (int j = 0; j < 14; ++j) {
            split_st(sb + O_VE_H + j*H + h, sb + O_VE_L + j*H + h, cE * w1[j]);
            split_st(sb + O_VD_H + j*H + h, sb + O_VD_L + j*H + h, cD * w2[j]);
        }
    }

    // ---- per-row constants and pointers ----
    const int b = blockIdx.x * MROWS + tid;
    const float Ev = Eg[b], nuv = nug[b];
    split_st(sb + O_X_H + tid*32 + 14, sb + O_X_L + tid*32 + 14, 1.0f);
    split_st(sb + O_X_H + tid*32 + 15, sb + O_X_L + tid*32 + 15, Ev);
    split_st(sb + O_X_H + tid*32 + 16, sb + O_X_L + tid*32 + 16, nuv);
    __syncthreads();

    const float* pe = e    + (size_t)b * TD;
    const float* pd = edot + (size_t)b * TD;
    float* so = out + (size_t)b * TD;
    float* xo = out + (size_t)B_TOT * TD + (size_t)b * (T_LEN * NIV);

    float xs[NIV];
#pragma unroll
    for (int j = 0; j < NIV; ++j) xs[j] = 0.f;

    float ce[6], cd[6];
#pragma unroll
    for (int j = 0; j < 6; ++j) { ce[j] = pe[j]; cd[j] = pd[j]; }

    __nv_bfloat16* xh = sb + O_X_H + tid * 32;
    __nv_bfloat16* xl = sb + O_X_L + tid * 32;

    for (int t = 0; t < T_LEN; ++t) {
        // xi output: state entering this step
#pragma unroll
        for (int j = 0; j < NIV; ++j) xo[t * NIV + j] = xs[j];

        // X_E = [e, xi, 1, E, nu]
#pragma unroll
        for (int j = 0; j < 6; ++j)   split_st(xh + j,     xl + j,     ce[j]);
#pragma unroll
        for (int j = 0; j < NIV; ++j) split_st(xh + 6 + j, xl + 6 + j, xs[j]);
        __syncwarp();

        // prefetch next step inputs
        float ne[6] = {0,0,0,0,0,0}, nd[6] = {0,0,0,0,0,0};
        if (t + 1 < T_LEN) {
            int o = (t + 1) * DE;
#pragma unroll
            for (int j = 0; j < 6; ++j) { ne[j] = pe[o + j]; nd[j] = pd[o + j]; }
        }

        // E-MLP
        mlp_pass(sb, sS, warp, lane, O_WE_H, O_WE_L, O_VE_H, O_VE_L);
        float ge[14];
#pragma unroll
        for (int j = 0; j < 14; ++j) ge[j] = sS[tid * 16 + j];

        // X_D = [edot, -d, 1, E, nu]
#pragma unroll
        for (int j = 0; j < 6; ++j)   split_st(xh + j,     xl + j,     cd[j]);
#pragma unroll
        for (int j = 0; j < NIV; ++j) split_st(xh + 6 + j, xl + 6 + j, -ge[6 + j]);
        __syncwarp();

        // D-MLP
        mlp_pass(sb, sS, warp, lane, O_WD_H, O_WD_L, O_VD_H, O_VD_L);

        // epilogue: stress = s_eq - s_neq; xi += DT * kinetics
#pragma unroll
        for (int j = 0; j < 6; ++j)
            so[t * DE + j] = ge[j] - sS[tid * 16 + j];
#pragma unroll
        for (int j = 0; j < NIV; ++j)
            xs[j] = fmaf(sS[tid * 16 + 6 + j], 0.01f, xs[j]);

#pragma unroll
        for (int j = 0; j < 6; ++j) { ce[j] = ne[j]; cd[j] = nd[j]; }
    }
}

extern "C" void kernel_launch(void* const* d_in, const int* in_sizes, int n_in,
                              void* d_out, int out_size) {
    const float* e    = (const float*)d_in[0];
    const float* edot = (const float*)d_in[1];
    const float* Eg   = (const float*)d_in[2];
    const float* nug  = (const float*)d_in[3];
    const float* We1  = (const float*)d_in[4];
    const float* be1  = (const float*)d_in[5];
    const float* We2  = (const float*)d_in[6];
    const float* Wd1  = (const float*)d_in[8];
    const float* bd1  = (const float*)d_in[9];
    const float* Wd2  = (const float*)d_in[10];
    const float* WE   = (const float*)d_in[12];
    const float* bE   = (const float*)d_in[13];
    const float* Wnu  = (const float*)d_in[14];
    const float* bnu  = (const float*)d_in[15];
    float* out = (float*)d_out;

    cudaFuncSetAttribute(visco_wmma, cudaFuncAttributeMaxDynamicSharedMemorySize, SMEM_TOTAL);
    visco_wmma<<<NCTA, 128, SMEM_TOTAL>>>(e, edot, Eg, nug, We1, be1, We2,
                                          Wd1, bd1, Wd2, WE, bE, Wnu, bnu, out);
}

// round 12
// speedup vs baseline: 6.4750x; 6.4750x over previous
#include <cuda_runtime.h>
#include <cuda_bf16.h>
#include <cstdint>

#define B_TOT 32768
#define T_LEN 200
#define DE    6
#define NIV   8
#define H     128
#define DIN   46
#define TD    (T_LEN*DE)
#define CHUNK 64          // rows per CTA pass (4 warps x 16 rows)
#define RUNS  (B_TOT/CHUNK)

__device__ unsigned g_run_ctr;
__global__ void reset_ctr_kernel() { g_run_ctr = 0u; }

// ---- m16n8k16 bf16 MMA, fp32 accumulate in place ----
static __device__ __forceinline__ void mma16816(float c[4], const uint32_t a[4], uint2 b) {
    asm volatile("mma.sync.aligned.m16n8k16.row.col.f32.bf16.bf16.f32 "
        "{%0,%1,%2,%3}, {%4,%5,%6,%7}, {%8,%9}, {%0,%1,%2,%3};"
        : "+f"(c[0]), "+f"(c[1]), "+f"(c[2]), "+f"(c[3])
        : "r"(a[0]), "r"(a[1]), "r"(a[2]), "r"(a[3]), "r"(b.x), "r"(b.y));
}

// pack (even, odd) floats -> bf16x2 with even in LOW half
static __device__ __forceinline__ uint32_t cvt2(float even, float odd) {
    uint32_t r;
    asm("cvt.rn.bf16x2.f32 %0, %1, %2;" : "=r"(r) : "f"(odd), "f"(even));
    return r;
}
// split pair into hi bf16x2 + lo (residual) bf16x2
static __device__ __forceinline__ void split2(float even, float odd, uint32_t& hi, uint32_t& lo) {
    hi = cvt2(even, odd);
    float he = __uint_as_float(hi << 16);
    float ho = __uint_as_float(hi & 0xFFFF0000u);
    lo = cvt2(even - he, odd - ho);
}
// scalar bf16 split -> bit patterns
static __device__ __forceinline__ void splits(float v, uint16_t& hb, uint16_t& lb) {
    __nv_bfloat16 h = __float2bfloat16(v);
    hb = __bfloat16_as_ushort(h);
    lb = __bfloat16_as_ushort(__float2bfloat16(v - __bfloat162float(h)));
}

__global__ void __launch_bounds__(128) visco_mma(
    const float* __restrict__ e,   const float* __restrict__ edot,
    const float* __restrict__ Eg,  const float* __restrict__ nug,
    const float* __restrict__ We1, const float* __restrict__ be1,
    const float* __restrict__ We2,
    const float* __restrict__ Wd1, const float* __restrict__ bd1,
    const float* __restrict__ Wd2,
    const float* __restrict__ WE,  const float* __restrict__ bE,
    const float* __restrict__ Wnu, const float* __restrict__ bnu,
    float* __restrict__ out)
{
    // B fragments pre-packed per lane: conflict-free LDS.64 in the loop
    __shared__ uint2  sBW[2][16][2][32];      // [mlp][ntile][hi/lo][lane]  GEMM1 W (K=16)
    __shared__ uint2  sBV[2][8][2][2][32];    // [mlp][ktile][ntile][hi/lo][lane] GEMM2 V
    __shared__ float2 sAP[2][64];             // alpha col-pairs
    __shared__ float  sABG[2][H][4];          // alpha, beta, gamma, 2c  (init only)
    __shared__ float  sSTG[4][16][16];        // per-warp staging (X build / ge readback)
    __shared__ unsigned sChunk;

    const int tid  = threadIdx.x;
    const int wrp  = tid >> 5;
    const int lane = tid & 31;
    const int g    = lane >> 2;
    const int t4   = lane & 3;

    // ---- init: derived per-h params ----
    {
        const int h = tid;
        const float* w1 = We1 + h * DIN;
        float a = be1[h], bt = 0.f, gm = 0.f;
#pragma unroll
        for (int k = 0; k < 16; ++k) { float w = w1[14 + k]; a += w * bE[k];  bt += w * WE[k]; }
#pragma unroll
        for (int k = 0; k < 16; ++k) { float w = w1[30 + k]; a += w * bnu[k]; gm += w * Wnu[k]; }
        sABG[0][h][0] = a; sABG[0][h][1] = bt; sABG[0][h][2] = gm;
        sABG[0][h][3] = 2.f * (We2[h] + We2[H + h]);
        ((float*)sAP)[0 * H + h] = a;

        const float* w2 = Wd1 + h * DIN;
        a = bd1[h]; bt = 0.f; gm = 0.f;
#pragma unroll
        for (int k = 0; k < 16; ++k) { float w = w2[14 + k]; a += w * bE[k];  bt += w * WE[k]; }
#pragma unroll
        for (int k = 0; k < 16; ++k) { float w = w2[30 + k]; a += w * bnu[k]; gm += w * Wnu[k]; }
        sABG[1][h][0] = a; sABG[1][h][1] = bt; sABG[1][h][2] = gm;
        sABG[1][h][3] = 2.f * Wd2[h];
        ((float*)sAP)[1 * H + h] = a;
    }
    __syncthreads();

    // ---- pack GEMM1 B fragments: B[k][h], k: 0-13 = W[h][k], 14 = beta, 15 = gamma ----
    for (int it = tid; it < 2 * 16 * 2 * 32; it += 128) {
        int ln = it & 31, hl = (it >> 5) & 1, nt = (it >> 6) & 15, m = it >> 10;
        int gg = ln >> 2, ttt = ln & 3, h = nt * 8 + gg;
        const float* W = (m ? Wd1 : We1) + h * DIN;
        int kk[4] = {2 * ttt, 2 * ttt + 1, 2 * ttt + 8, 2 * ttt + 9};
        uint16_t s[4];
#pragma unroll
        for (int i = 0; i < 4; ++i) {
            int k = kk[i];
            float v = (k < 14) ? W[k] : ((k == 14) ? sABG[m][h][1] : sABG[m][h][2]);
            uint16_t hb, lb; splits(v, hb, lb);
            s[i] = hl ? lb : hb;
        }
        sBW[m][nt][hl][ln] = make_uint2((uint32_t)s[0] | ((uint32_t)s[1] << 16),
                                        (uint32_t)s[2] | ((uint32_t)s[3] << 16));
    }
    // ---- pack GEMM2 B fragments: V[h][n] = 2c_h * W[h][n], n<14 else 0 ----
    for (int it = tid; it < 2 * 8 * 2 * 2 * 32; it += 128) {
        int ln = it & 31, hl = (it >> 5) & 1, nt = (it >> 6) & 1, kt = (it >> 7) & 7, m = it >> 10;
        int gg = ln >> 2, ttt = ln & 3, n = nt * 8 + gg;
        const float* W = m ? Wd1 : We1;
        int hs[4] = {kt * 16 + 2 * ttt, kt * 16 + 2 * ttt + 1,
                     kt * 16 + 2 * ttt + 8, kt * 16 + 2 * ttt + 9};
        uint16_t s[4];
#pragma unroll
        for (int i = 0; i < 4; ++i) {
            float v = (n < 14) ? sABG[m][hs[i]][3] * W[hs[i] * DIN + n] : 0.f;
            uint16_t hb, lb; splits(v, hb, lb);
            s[i] = hl ? lb : hb;
        }
        sBV[m][kt][nt][hl][ln] = make_uint2((uint32_t)s[0] | ((uint32_t)s[1] << 16),
                                            (uint32_t)s[2] | ((uint32_t)s[3] << 16));
    }
    __syncthreads();

    float (*stg)[16] = sSTG[wrp];
    const bool own = (lane < 16);

    for (;;) {
        if (tid == 0) sChunk = atomicAdd(&g_run_ctr, 1u);
        __syncthreads();
        unsigned chunk = sChunk;
        __syncthreads();
        if (chunk >= RUNS) break;

        const int b = (int)chunk * CHUNK + wrp * 16 + lane;   // valid for lane<16
        float Ev = 0.f, nv = 0.f;
        const float *pe = nullptr, *pd = nullptr;
        float *so = nullptr, *xo = nullptr;
        float ce[6], cd[6], xs[NIV];
#pragma unroll
        for (int j = 0; j < NIV; ++j) xs[j] = 0.f;
        if (own) {
            Ev = Eg[b]; nv = nug[b];
            pe = e + (size_t)b * TD;  pd = edot + (size_t)b * TD;
            so = out + (size_t)b * TD;
            xo = out + (size_t)B_TOT * TD + (size_t)b * (T_LEN * NIV);
#pragma unroll
            for (int j = 0; j < 6; ++j) { ce[j] = pe[j]; cd[j] = pd[j]; }
        }

        for (int t = 0; t < T_LEN; ++t) {
            // xi out (state entering step) + X_E staging
            if (own) {
                *(float4*)(xo + t * NIV)     = make_float4(xs[0], xs[1], xs[2], xs[3]);
                *(float4*)(xo + t * NIV + 4) = make_float4(xs[4], xs[5], xs[6], xs[7]);
                float* r = stg[lane];
                *(float4*)(r)      = make_float4(ce[0], ce[1], ce[2], ce[3]);
                *(float4*)(r + 4)  = make_float4(ce[4], ce[5], xs[0], xs[1]);
                *(float4*)(r + 8)  = make_float4(xs[2], xs[3], xs[4], xs[5]);
                *(float4*)(r + 12) = make_float4(xs[6], xs[7], Ev, nv);
            }
            __syncwarp();

            // prefetch next inputs (owner only)
            float ne[6], nd[6];
            if (own && t + 1 < T_LEN) {
                const int o = (t + 1) * DE;
#pragma unroll
                for (int j = 0; j < 6; j += 2) {
                    float2 v1 = *(const float2*)(pe + o + j); ne[j] = v1.x; ne[j + 1] = v1.y;
                    float2 v2 = *(const float2*)(pd + o + j); nd[j] = v2.x; nd[j + 1] = v2.y;
                }
            }

            float geE[14];
#pragma unroll
            for (int m = 0; m < 2; ++m) {
                // build X A-fragments (hi/lo) from staging
                uint32_t aH[4], aL[4];
                {
                    float2 r0 = *(const float2*)&stg[g][2 * t4];
                    float2 r1 = *(const float2*)&stg[g + 8][2 * t4];
                    float2 r2 = *(const float2*)&stg[g][2 * t4 + 8];
                    float2 r3 = *(const float2*)&stg[g + 8][2 * t4 + 8];
                    split2(r0.x, r0.y, aH[0], aL[0]);
                    split2(r1.x, r1.y, aH[1], aL[1]);
                    split2(r2.x, r2.y, aH[2], aL[2]);
                    split2(r3.x, r3.y, aH[3], aL[3]);
                }
                __syncwarp();   // staging reads done before epilogue STS below

                // GEMM1: P = X @ W^T (+alpha bias), relu, split -> GEMM2 A-fragments
                uint32_t RAh[8][4], RAl[8][4];
#pragma unroll
                for (int j = 0; j < 8; ++j) {
                    uint2 b0h = sBW[m][2 * j][0][lane],     b0l = sBW[m][2 * j][1][lane];
                    uint2 b1h = sBW[m][2 * j + 1][0][lane], b1l = sBW[m][2 * j + 1][1][lane];
                    float c0[4] = {0.f, 0.f, 0.f, 0.f}, c1[4] = {0.f, 0.f, 0.f, 0.f};
                    mma16816(c0, aH, b0h); mma16816(c0, aH, b0l); mma16816(c0, aL, b0h);
                    mma16816(c1, aH, b1h); mma16816(c1, aH, b1l); mma16816(c1, aL, b1h);
                    float2 A0 = sAP[m][8 * j + t4];
                    float2 A1 = sAP[m][8 * j + 4 + t4];
                    c0[0] = fmaxf(c0[0] + A0.x, 0.f); c0[1] = fmaxf(c0[1] + A0.y, 0.f);
                    c0[2] = fmaxf(c0[2] + A0.x, 0.f); c0[3] = fmaxf(c0[3] + A0.y, 0.f);
                    c1[0] = fmaxf(c1[0] + A1.x, 0.f); c1[1] = fmaxf(c1[1] + A1.y, 0.f);
                    c1[2] = fmaxf(c1[2] + A1.x, 0.f); c1[3] = fmaxf(c1[3] + A1.y, 0.f);
                    split2(c0[0], c0[1], RAh[j][0], RAl[j][0]);
                    split2(c0[2], c0[3], RAh[j][1], RAl[j][1]);
                    split2(c1[0], c1[1], RAh[j][2], RAl[j][2]);
                    split2(c1[2], c1[3], RAh[j][3], RAl[j][3]);
                }

                // GEMM2: ge = R @ V^T  (K=128)
                float d0[4] = {0.f, 0.f, 0.f, 0.f}, d1[4] = {0.f, 0.f, 0.f, 0.f};
#pragma unroll
                for (int kt = 0; kt < 8; ++kt) {
                    uint2 v0h = sBV[m][kt][0][0][lane], v0l = sBV[m][kt][0][1][lane];
                    uint2 v1h = sBV[m][kt][1][0][lane], v1l = sBV[m][kt][1][1][lane];
                    mma16816(d0, RAh[kt], v0h); mma16816(d0, RAh[kt], v0l); mma16816(d0, RAl[kt], v0h);
                    mma16816(d1, RAh[kt], v1h); mma16816(d1, RAh[kt], v1l); mma16816(d1, RAl[kt], v1h);
                }
                // store ge to staging
                *(float2*)&stg[g][2 * t4]         = make_float2(d0[0], d0[1]);
                *(float2*)&stg[g + 8][2 * t4]     = make_float2(d0[2], d0[3]);
                *(float2*)&stg[g][2 * t4 + 8]     = make_float2(d1[0], d1[1]);
                *(float2*)&stg[g + 8][2 * t4 + 8] = make_float2(d1[2], d1[3]);
                __syncwarp();

                if (m == 0) {
                    // read geE row; build X_D staging
                    if (own) {
                        const float* r = stg[lane];
#pragma unroll
                        for (int j = 0; j < 14; ++j) geE[j] = r[j];
                        float* w = stg[lane];
                        *(float4*)(w)      = make_float4(cd[0], cd[1], cd[2], cd[3]);
                        *(float4*)(w + 4)  = make_float4(cd[4], cd[5], -geE[6], -geE[7]);
                        *(float4*)(w + 8)  = make_float4(-geE[8], -geE[9], -geE[10], -geE[11]);
                        *(float4*)(w + 12) = make_float4(-geE[12], -geE[13], Ev, nv);
                    }
                    __syncwarp();
                } else {
                    // epilogue: stress = geE - geD; xi += DT*geD[6..13]
                    if (own) {
                        const float* r = stg[lane];
                        float* s = so + t * DE;
                        *(float2*)(s)     = make_float2(geE[0] - r[0], geE[1] - r[1]);
                        *(float2*)(s + 2) = make_float2(geE[2] - r[2], geE[3] - r[3]);
                        *(float2*)(s + 4) = make_float2(geE[4] - r[4], geE[5] - r[5]);
#pragma unroll
                        for (int j = 0; j < NIV; ++j)
                            xs[j] = fmaf(r[6 + j], 0.01f, xs[j]);
                    }
                    __syncwarp();
                }
            }

            if (own) {
#pragma unroll
                for (int j = 0; j < 6; ++j) { ce[j] = ne[j]; cd[j] = nd[j]; }
            }
        }
        __syncthreads();
    }
}

extern "C" void kernel_launch(void* const* d_in, const int* in_sizes, int n_in,
                              void* d_out, int out_size) {
    const float* e    = (const float*)d_in[0];
    const float* edot = (const float*)d_in[1];
    const float* Eg   = (const float*)d_in[2];
    const float* nug  = (const float*)d_in[3];
    const float* We1  = (const float*)d_in[4];
    const float* be1  = (const float*)d_in[5];
    const float* We2  = (const float*)d_in[6];
    const float* Wd1  = (const float*)d_in[8];
    const float* bd1  = (const float*)d_in[9];
    const float* Wd2  = (const float*)d_in[10];
    const float* WE   = (const float*)d_in[12];
    const float* bE   = (const float*)d_in[13];
    const float* Wnu  = (const float*)d_in[14];
    const float* bnu  = (const float*)d_in[15];
    float* out = (float*)d_out;

    reset_ctr_kernel<<<1, 1>>>();
    visco_mma<<<444, 128>>>(e, edot, Eg, nug, We1, be1, We2,
                            Wd1, bd1, Wd2, WE, bE, Wnu, bnu, out);
}

// round 13
// speedup vs baseline: 7.4110x; 1.1446x over previous
#include <cuda_runtime.h>
#include <cuda_bf16.h>
#include <cstdint>

#define B_TOT 32768
#define T_LEN 200
#define DE    6
#define NIV   8
#define H     128
#define DIN   46
#define TD    (T_LEN*DE)
#define NCTA  (B_TOT/128)     // 256 blocks, 32 rows per warp

struct SmemT {
    uint2  BW[2][16][2][32];      // [mlp][ntile][hi/lo][lane]  GEMM1 W frags (K=16)
    uint2  BV[2][8][2][2][32];    // [mlp][ktile][ntile][hi/lo][lane] GEMM2 V frags
    float2 AP[2][64];             // alpha col-pairs
    float  STG[4][32][16];        // per-warp staging: X / geD
    float  STE[4][32][16];        // per-warp staging: geE
};
#define SMEM_TOTAL ((int)sizeof(SmemT))

// ---- m16n8k16 bf16 MMA, fp32 accumulate in place ----
static __device__ __forceinline__ void mma16816(float c[4], const uint32_t a[4], uint2 b) {
    asm volatile("mma.sync.aligned.m16n8k16.row.col.f32.bf16.bf16.f32 "
        "{%0,%1,%2,%3}, {%4,%5,%6,%7}, {%8,%9}, {%0,%1,%2,%3};"
        : "+f"(c[0]), "+f"(c[1]), "+f"(c[2]), "+f"(c[3])
        : "r"(a[0]), "r"(a[1]), "r"(a[2]), "r"(a[3]), "r"(b.x), "r"(b.y));
}
static __device__ __forceinline__ uint32_t cvt2(float even, float odd) {
    uint32_t r;
    asm("cvt.rn.bf16x2.f32 %0, %1, %2;" : "=r"(r) : "f"(odd), "f"(even));
    return r;
}
static __device__ __forceinline__ void split2(float even, float odd, uint32_t& hi, uint32_t& lo) {
    hi = cvt2(even, odd);
    float he = __uint_as_float(hi << 16);
    float ho = __uint_as_float(hi & 0xFFFF0000u);
    lo = cvt2(even - he, odd - ho);
}
static __device__ __forceinline__ void splits(float v, uint16_t& hb, uint16_t& lb) {
    __nv_bfloat16 h = __float2bfloat16(v);
    hb = __bfloat16_as_ushort(h);
    lb = __bfloat16_as_ushort(__float2bfloat16(v - __bfloat162float(h)));
}

__global__ void __launch_bounds__(128) visco_mma(
    const float* __restrict__ e,   const float* __restrict__ edot,
    const float* __restrict__ Eg,  const float* __restrict__ nug,
    const float* __restrict__ We1, const float* __restrict__ be1,
    const float* __restrict__ We2,
    const float* __restrict__ Wd1, const float* __restrict__ bd1,
    const float* __restrict__ Wd2,
    const float* __restrict__ WE,  const float* __restrict__ bE,
    const float* __restrict__ Wnu, const float* __restrict__ bnu,
    float* __restrict__ out)
{
    extern __shared__ __align__(16) char smraw[];
    SmemT* S = reinterpret_cast<SmemT*>(smraw);

    const int tid  = threadIdx.x;
    const int wrp  = tid >> 5;
    const int lane = tid & 31;
    const int g    = lane >> 2;
    const int t4   = lane & 3;

    // ABG scratch aliased into STG (used only during init)
    float (*ABG)[4] = reinterpret_cast<float(*)[4]>(&S->STG[0][0][0]);   // [2*H][4]

    // ---- init: derived per-h params ----
    {
        const int h = tid;
        const float* w1 = We1 + h * DIN;
        float a = be1[h], bt = 0.f, gm = 0.f;
#pragma unroll
        for (int k = 0; k < 16; ++k) { float w = w1[14 + k]; a += w * bE[k];  bt += w * WE[k]; }
#pragma unroll
        for (int k = 0; k < 16; ++k) { float w = w1[30 + k]; a += w * bnu[k]; gm += w * Wnu[k]; }
        ABG[0 * H + h][0] = a; ABG[0 * H + h][1] = bt; ABG[0 * H + h][2] = gm;
        ABG[0 * H + h][3] = 2.f * (We2[h] + We2[H + h]);
        ((float*)S->AP)[0 * H + h] = a;

        const float* w2 = Wd1 + h * DIN;
        a = bd1[h]; bt = 0.f; gm = 0.f;
#pragma unroll
        for (int k = 0; k < 16; ++k) { float w = w2[14 + k]; a += w * bE[k];  bt += w * WE[k]; }
#pragma unroll
        for (int k = 0; k < 16; ++k) { float w = w2[30 + k]; a += w * bnu[k]; gm += w * Wnu[k]; }
        ABG[1 * H + h][0] = a; ABG[1 * H + h][1] = bt; ABG[1 * H + h][2] = gm;
        ABG[1 * H + h][3] = 2.f * Wd2[h];
        ((float*)S->AP)[1 * H + h] = a;
    }
    __syncthreads();

    // ---- pack GEMM1 B fragments: k 0-13 = W[h][k], 14 = beta, 15 = gamma ----
    for (int it = tid; it < 2 * 16 * 2 * 32; it += 128) {
        int ln = it & 31, hl = (it >> 5) & 1, nt = (it >> 6) & 15, m = it >> 10;
        int gg = ln >> 2, ttt = ln & 3, h = nt * 8 + gg;
        const float* W = (m ? Wd1 : We1) + h * DIN;
        int kk[4] = {2 * ttt, 2 * ttt + 1, 2 * ttt + 8, 2 * ttt + 9};
        uint16_t s[4];
#pragma unroll
        for (int i = 0; i < 4; ++i) {
            int k = kk[i];
            float v = (k < 14) ? W[k] : ((k == 14) ? ABG[m * H + h][1] : ABG[m * H + h][2]);
            uint16_t hb, lb; splits(v, hb, lb);
            s[i] = hl ? lb : hb;
        }
        S->BW[m][nt][hl][ln] = make_uint2((uint32_t)s[0] | ((uint32_t)s[1] << 16),
                                          (uint32_t)s[2] | ((uint32_t)s[3] << 16));
    }
    // ---- pack GEMM2 B fragments: V[h][n] = 2c_h * W[h][n], n<14 else 0 ----
    for (int it = tid; it < 2 * 8 * 2 * 2 * 32; it += 128) {
        int ln = it & 31, hl = (it >> 5) & 1, nt = (it >> 6) & 1, kt = (it >> 7) & 7, m = it >> 10;
        int gg = ln >> 2, ttt = ln & 3, n = nt * 8 + gg;
        const float* W = m ? Wd1 : We1;
        int hs[4] = {kt * 16 + 2 * ttt, kt * 16 + 2 * ttt + 1,
                     kt * 16 + 2 * ttt + 8, kt * 16 + 2 * ttt + 9};
        uint16_t s[4];
#pragma unroll
        for (int i = 0; i < 4; ++i) {
            float v = (n < 14) ? ABG[m * H + hs[i]][3] * W[hs[i] * DIN + n] : 0.f;
            uint16_t hb, lb; splits(v, hb, lb);
            s[i] = hl ? lb : hb;
        }
        S->BV[m][kt][nt][hl][ln] = make_uint2((uint32_t)s[0] | ((uint32_t)s[1] << 16),
                                              (uint32_t)s[2] | ((uint32_t)s[3] << 16));
    }
    __syncthreads();

    // ---- per-lane row ownership: warp owns 32 rows, lane owns one ----
    const int b = blockIdx.x * 128 + wrp * 32 + lane;
    const float Ev = Eg[b], nv = nug[b];
    const float* pe = e    + (size_t)b * TD;
    const float* pd = edot + (size_t)b * TD;
    float* so = out + (size_t)b * TD;
    float* xo = out + (size_t)B_TOT * TD + (size_t)b * (T_LEN * NIV);

    float xs[NIV];
#pragma unroll
    for (int j = 0; j < NIV; ++j) xs[j] = 0.f;
    float ce[6], cd[6];
#pragma unroll
    for (int j = 0; j < 6; ++j) { ce[j] = pe[j]; cd[j] = pd[j]; }

    float (*stg)[16] = S->STG[wrp];
    float (*ste)[16] = S->STE[wrp];

    for (int t = 0; t < T_LEN; ++t) {
        // xi out (state entering step) + X_E staging (every lane owns a row)
        *(float4*)(xo + t * NIV)     = make_float4(xs[0], xs[1], xs[2], xs[3]);
        *(float4*)(xo + t * NIV + 4) = make_float4(xs[4], xs[5], xs[6], xs[7]);
        {
            float* r = stg[lane];
            *(float4*)(r)      = make_float4(ce[0], ce[1], ce[2], ce[3]);
            *(float4*)(r + 4)  = make_float4(ce[4], ce[5], xs[0], xs[1]);
            *(float4*)(r + 8)  = make_float4(xs[2], xs[3], xs[4], xs[5]);
            *(float4*)(r + 12) = make_float4(xs[6], xs[7], Ev, nv);
        }
        __syncwarp();

#pragma unroll
        for (int m = 0; m < 2; ++m) {
            // A fragments for both m-tiles (rows 0-15 and 16-31 of this warp)
            uint32_t aH0[4], aL0[4], aH1[4], aL1[4];
            {
                float2 r0 = *(const float2*)&stg[g][2 * t4];
                float2 r1 = *(const float2*)&stg[g + 8][2 * t4];
                float2 r2 = *(const float2*)&stg[g][2 * t4 + 8];
                float2 r3 = *(const float2*)&stg[g + 8][2 * t4 + 8];
                split2(r0.x, r0.y, aH0[0], aL0[0]);
                split2(r1.x, r1.y, aH0[1], aL0[1]);
                split2(r2.x, r2.y, aH0[2], aL0[2]);
                split2(r3.x, r3.y, aH0[3], aL0[3]);
                r0 = *(const float2*)&stg[16 + g][2 * t4];
                r1 = *(const float2*)&stg[24 + g][2 * t4];
                r2 = *(const float2*)&stg[16 + g][2 * t4 + 8];
                r3 = *(const float2*)&stg[24 + g][2 * t4 + 8];
                split2(r0.x, r0.y, aH1[0], aL1[0]);
                split2(r1.x, r1.y, aH1[1], aL1[1]);
                split2(r2.x, r2.y, aH1[2], aL1[2]);
                split2(r3.x, r3.y, aH1[3], aL1[3]);
            }
            __syncwarp();

            // GEMM1: P = X @ W^T (+alpha), relu, split -> GEMM2 A frags (both m-tiles)
            uint32_t RAh0[8][4], RAl0[8][4], RAh1[8][4], RAl1[8][4];
#pragma unroll
            for (int j = 0; j < 8; ++j) {
                uint2 b0h = S->BW[m][2 * j][0][lane],     b0l = S->BW[m][2 * j][1][lane];
                uint2 b1h = S->BW[m][2 * j + 1][0][lane], b1l = S->BW[m][2 * j + 1][1][lane];
                float2 A0 = S->AP[m][8 * j + t4];
                float2 A1 = S->AP[m][8 * j + 4 + t4];

                float c0[4] = {0.f, 0.f, 0.f, 0.f}, c1[4] = {0.f, 0.f, 0.f, 0.f};
                mma16816(c0, aH0, b0h); mma16816(c0, aH0, b0l); mma16816(c0, aL0, b0h);
                mma16816(c1, aH0, b1h); mma16816(c1, aH0, b1l); mma16816(c1, aL0, b1h);
                c0[0] = fmaxf(c0[0] + A0.x, 0.f); c0[1] = fmaxf(c0[1] + A0.y, 0.f);
                c0[2] = fmaxf(c0[2] + A0.x, 0.f); c0[3] = fmaxf(c0[3] + A0.y, 0.f);
                c1[0] = fmaxf(c1[0] + A1.x, 0.f); c1[1] = fmaxf(c1[1] + A1.y, 0.f);
                c1[2] = fmaxf(c1[2] + A1.x, 0.f); c1[3] = fmaxf(c1[3] + A1.y, 0.f);
                split2(c0[0], c0[1], RAh0[j][0], RAl0[j][0]);
                split2(c0[2], c0[3], RAh0[j][1], RAl0[j][1]);
                split2(c1[0], c1[1], RAh0[j][2], RAl0[j][2]);
                split2(c1[2], c1[3], RAh0[j][3], RAl0[j][3]);

                float e0[4] = {0.f, 0.f, 0.f, 0.f}, e1[4] = {0.f, 0.f, 0.f, 0.f};
                mma16816(e0, aH1, b0h); mma16816(e0, aH1, b0l); mma16816(e0, aL1, b0h);
                mma16816(e1, aH1, b1h); mma16816(e1, aH1, b1l); mma16816(e1, aL1, b1h);
                e0[0] = fmaxf(e0[0] + A0.x, 0.f); e0[1] = fmaxf(e0[1] + A0.y, 0.f);
                e0[2] = fmaxf(e0[2] + A0.x, 0.f); e0[3] = fmaxf(e0[3] + A0.y, 0.f);
                e1[0] = fmaxf(e1[0] + A1.x, 0.f); e1[1] = fmaxf(e1[1] + A1.y, 0.f);
                e1[2] = fmaxf(e1[2] + A1.x, 0.f); e1[3] = fmaxf(e1[3] + A1.y, 0.f);
                split2(e0[0], e0[1], RAh1[j][0], RAl1[j][0]);
                split2(e0[2], e0[3], RAh1[j][1], RAl1[j][1]);
                split2(e1[0], e1[1], RAh1[j][2], RAl1[j][2]);
                split2(e1[2], e1[3], RAh1[j][3], RAl1[j][3]);
            }

            // GEMM2: ge = R @ V^T (K=128), both m-tiles share B loads
            float d00[4] = {0.f,0.f,0.f,0.f}, d01[4] = {0.f,0.f,0.f,0.f};
            float d10[4] = {0.f,0.f,0.f,0.f}, d11[4] = {0.f,0.f,0.f,0.f};
#pragma unroll
            for (int kt = 0; kt < 8; ++kt) {
                uint2 v0h = S->BV[m][kt][0][0][lane], v0l = S->BV[m][kt][0][1][lane];
                uint2 v1h = S->BV[m][kt][1][0][lane], v1l = S->BV[m][kt][1][1][lane];
                mma16816(d00, RAh0[kt], v0h); mma16816(d00, RAh0[kt], v0l); mma16816(d00, RAl0[kt], v0h);
                mma16816(d01, RAh0[kt], v1h); mma16816(d01, RAh0[kt], v1l); mma16816(d01, RAl0[kt], v1h);
                mma16816(d10, RAh1[kt], v0h); mma16816(d10, RAh1[kt], v0l); mma16816(d10, RAl1[kt], v0h);
                mma16816(d11, RAh1[kt], v1h); mma16816(d11, RAh1[kt], v1l); mma16816(d11, RAl1[kt], v1h);
            }

            // store ge:  m==0 -> STE (geE),  m==1 -> STG (geD)
            float (*dst)[16] = m ? stg : ste;
            *(float2*)&dst[g][2 * t4]          = make_float2(d00[0], d00[1]);
            *(float2*)&dst[g + 8][2 * t4]      = make_float2(d00[2], d00[3]);
            *(float2*)&dst[g][2 * t4 + 8]      = make_float2(d01[0], d01[1]);
            *(float2*)&dst[g + 8][2 * t4 + 8]  = make_float2(d01[2], d01[3]);
            *(float2*)&dst[16 + g][2 * t4]     = make_float2(d10[0], d10[1]);
            *(float2*)&dst[24 + g][2 * t4]     = make_float2(d10[2], d10[3]);
            *(float2*)&dst[16 + g][2 * t4 + 8] = make_float2(d11[0], d11[1]);
            *(float2*)&dst[24 + g][2 * t4 + 8] = make_float2(d11[2], d11[3]);
            __syncwarp();

            if (m == 0) {
                // X_D = [edot, -d, E, nu]; then prefetch t+1 inputs (reuse ce/cd)
                const float* r = ste[lane];
                float* w = stg[lane];
                *(float4*)(w)      = make_float4(cd[0], cd[1], cd[2], cd[3]);
                *(float4*)(w + 4)  = make_float4(cd[4], cd[5], -r[6], -r[7]);
                *(float4*)(w + 8)  = make_float4(-r[8], -r[9], -r[10], -r[11]);
                *(float4*)(w + 12) = make_float4(-r[12], -r[13], Ev, nv);
                if (t + 1 < T_LEN) {
                    const int o = (t + 1) * DE;
#pragma unroll
                    for (int j = 0; j < 6; j += 2) {
                        float2 v1 = *(const float2*)(pe + o + j); ce[j] = v1.x; ce[j + 1] = v1.y;
                        float2 v2 = *(const float2*)(pd + o + j); cd[j] = v2.x; cd[j + 1] = v2.y;
                    }
                }
                __syncwarp();
            }
        }

        // epilogue: stress = geE - geD; xi += DT * geD[6..13]
        {
            const float* rE = ste[lane];
            const float* rD = stg[lane];
            float* s = so + t * DE;
            *(float2*)(s)     = make_float2(rE[0] - rD[0], rE[1] - rD[1]);
            *(float2*)(s + 2) = make_float2(rE[2] - rD[2], rE[3] - rD[3]);
            *(float2*)(s + 4) = make_float2(rE[4] - rD[4], rE[5] - rD[5]);
#pragma unroll
            for (int j = 0; j < NIV; ++j)
                xs[j] = fmaf(rD[6 + j], 0.01f, xs[j]);
        }
    }
}

extern "C" void kernel_launch(void* const* d_in, const int* in_sizes, int n_in,
                              void* d_out, int out_size) {
    const float* e    = (const float*)d_in[0];
    const float* edot = (const float*)d_in[1];
    const float* Eg   = (const float*)d_in[2];
    const float* nug  = (const float*)d_in[3];
    const float* We1  = (const float*)d_in[4];
    const float* be1  = (const float*)d_in[5];
    const float* We2  = (const float*)d_in[6];
    const float* Wd1  = (const float*)d_in[8];
    const float* bd1  = (const float*)d_in[9];
    const float* Wd2  = (const float*)d_in[10];
    const float* WE   = (const float*)d_in[12];
    const float* bE   = (const float*)d_in[13];
    const float* Wnu  = (const float*)d_in[14];
    const float* bnu  = (const float*)d_in[15];
    float* out = (float*)d_out;

    cudaFuncSetAttribute(visco_mma, cudaFuncAttributeMaxDynamicSharedMemorySize, SMEM_TOTAL);
    visco_mma<<<NCTA, 128, SMEM_TOTAL>>>(e, edot, Eg, nug, We1, be1, We2,
                                         Wd1, bd1, Wd2, WE, bE, Wnu, bnu, out);
}

// round 14
// speedup vs baseline: 8.5400x; 1.1523x over previous
#include <cuda_runtime.h>
#include <cuda_bf16.h>
#include <cstdint>

#define B_TOT 32768
#define T_LEN 200
#define DE    6
#define NIV   8
#define H     128
#define DIN   46
#define TD    (T_LEN*DE)
#define NCTA  (B_TOT/128)     // 256 blocks, 4 warps x 32 rows

struct SmemT {
    uint4  BW[2][16][32];       // [mlp][ntile][lane]: (hi.x,hi.y,lo.x,lo.y) GEMM1 W frags
    uint4  BV[2][8][2][32];     // [mlp][ktile][ntile][lane] GEMM2 V frags
    float2 AP[2][64];           // alpha pairs
    uint2  STGE[4][32][4];      // per-warp: pre-split [e(6),E,nu] (hi,lo) pairs
    uint2  STGD[4][32][4];      // per-warp: pre-split [edot(6),E,nu]
};

static __device__ __forceinline__ void mma16816(float c[4], const uint32_t a[4], uint2 b) {
    asm volatile("mma.sync.aligned.m16n8k16.row.col.f32.bf16.bf16.f32 "
        "{%0,%1,%2,%3}, {%4,%5,%6,%7}, {%8,%9}, {%0,%1,%2,%3};"
        : "+f"(c[0]), "+f"(c[1]), "+f"(c[2]), "+f"(c[3])
        : "r"(a[0]), "r"(a[1]), "r"(a[2]), "r"(a[3]), "r"(b.x), "r"(b.y));
}
static __device__ __forceinline__ uint32_t cvt2(float even, float odd) {
    uint32_t r;
    asm("cvt.rn.bf16x2.f32 %0, %1, %2;" : "=r"(r) : "f"(odd), "f"(even));
    return r;
}
static __device__ __forceinline__ void split2(float even, float odd, uint32_t& hi, uint32_t& lo) {
    hi = cvt2(even, odd);
    float he = __uint_as_float(hi << 16);
    float ho = __uint_as_float(hi & 0xFFFF0000u);
    lo = cvt2(even - he, odd - ho);
}
static __device__ __forceinline__ void splits(float v, uint16_t& hb, uint16_t& lb) {
    __nv_bfloat16 h = __float2bfloat16(v);
    hb = __bfloat16_as_ushort(h);
    lb = __bfloat16_as_ushort(__float2bfloat16(v - __bfloat162float(h)));
}

// One MLP (GEMM1 + relu + GEMM2) for a warp's 32 rows, fully fragment-resident.
// Outputs: dT0/dT1 = n-tile0 C-frags (d or kinetics), sT0/sT1 = n-tile1 (s cols).
static __device__ __forceinline__ void mlp_tc(
    const SmemT* __restrict__ S, int m, int lane, int t4,
    const uint32_t aH0[4], const uint32_t aL0[4],
    const uint32_t aH1[4], const uint32_t aL1[4],
    float dT0[4], float sT0[4], float dT1[4], float sT1[4])
{
    uint32_t RAh0[8][4], RAl0[8][4], RAh1[8][4], RAl1[8][4];
#pragma unroll
    for (int j = 0; j < 8; ++j) {
        uint4 w0 = S->BW[m][2 * j][lane];
        uint4 w1 = S->BW[m][2 * j + 1][lane];
        float2 A0 = S->AP[m][8 * j + t4];
        float2 A1 = S->AP[m][8 * j + 4 + t4];
        uint2 w0h = make_uint2(w0.x, w0.y), w0l = make_uint2(w0.z, w0.w);
        uint2 w1h = make_uint2(w1.x, w1.y), w1l = make_uint2(w1.z, w1.w);

        float c0[4] = {0.f,0.f,0.f,0.f}, c1[4] = {0.f,0.f,0.f,0.f};
        float f0[4] = {0.f,0.f,0.f,0.f}, f1[4] = {0.f,0.f,0.f,0.f};
        mma16816(c0, aH0, w0h); mma16816(c0, aH0, w0l); mma16816(c0, aL0, w0h);
        mma16816(c1, aH0, w1h); mma16816(c1, aH0, w1l); mma16816(c1, aL0, w1h);
        mma16816(f0, aH1, w0h); mma16816(f0, aH1, w0l); mma16816(f0, aL1, w0h);
        mma16816(f1, aH1, w1h); mma16816(f1, aH1, w1l); mma16816(f1, aL1, w1h);

        c0[0] = fmaxf(c0[0] + A0.x, 0.f); c0[1] = fmaxf(c0[1] + A0.y, 0.f);
        c0[2] = fmaxf(c0[2] + A0.x, 0.f); c0[3] = fmaxf(c0[3] + A0.y, 0.f);
        c1[0] = fmaxf(c1[0] + A1.x, 0.f); c1[1] = fmaxf(c1[1] + A1.y, 0.f);
        c1[2] = fmaxf(c1[2] + A1.x, 0.f); c1[3] = fmaxf(c1[3] + A1.y, 0.f);
        f0[0] = fmaxf(f0[0] + A0.x, 0.f); f0[1] = fmaxf(f0[1] + A0.y, 0.f);
        f0[2] = fmaxf(f0[2] + A0.x, 0.f); f0[3] = fmaxf(f0[3] + A0.y, 0.f);
        f1[0] = fmaxf(f1[0] + A1.x, 0.f); f1[1] = fmaxf(f1[1] + A1.y, 0.f);
        f1[2] = fmaxf(f1[2] + A1.x, 0.f); f1[3] = fmaxf(f1[3] + A1.y, 0.f);

        split2(c0[0], c0[1], RAh0[j][0], RAl0[j][0]);
        split2(c0[2], c0[3], RAh0[j][1], RAl0[j][1]);
        split2(c1[0], c1[1], RAh0[j][2], RAl0[j][2]);
        split2(c1[2], c1[3], RAh0[j][3], RAl0[j][3]);
        split2(f0[0], f0[1], RAh1[j][0], RAl1[j][0]);
        split2(f0[2], f0[3], RAh1[j][1], RAl1[j][1]);
        split2(f1[0], f1[1], RAh1[j][2], RAl1[j][2]);
        split2(f1[2], f1[3], RAh1[j][3], RAl1[j][3]);
    }

#pragma unroll
    for (int i = 0; i < 4; ++i) { dT0[i] = 0.f; sT0[i] = 0.f; dT1[i] = 0.f; sT1[i] = 0.f; }
#pragma unroll
    for (int kt = 0; kt < 8; ++kt) {
        uint4 v0 = S->BV[m][kt][0][lane];
        uint4 v1 = S->BV[m][kt][1][lane];
        uint2 v0h = make_uint2(v0.x, v0.y), v0l = make_uint2(v0.z, v0.w);
        uint2 v1h = make_uint2(v1.x, v1.y), v1l = make_uint2(v1.z, v1.w);
        mma16816(dT0, RAh0[kt], v0h); mma16816(dT0, RAh0[kt], v0l); mma16816(dT0, RAl0[kt], v0h);
        mma16816(sT0, RAh0[kt], v1h); mma16816(sT0, RAh0[kt], v1l); mma16816(sT0, RAl0[kt], v1h);
        mma16816(dT1, RAh1[kt], v0h); mma16816(dT1, RAh1[kt], v0l); mma16816(dT1, RAl1[kt], v0h);
        mma16816(sT1, RAh1[kt], v1h); mma16816(sT1, RAh1[kt], v1l); mma16816(sT1, RAl1[kt], v1h);
    }
}

__global__ void __launch_bounds__(128) visco_mma(
    const float* __restrict__ e,   const float* __restrict__ edot,
    const float* __restrict__ Eg,  const float* __restrict__ nug,
    const float* __restrict__ We1, const float* __restrict__ be1,
    const float* __restrict__ We2,
    const float* __restrict__ Wd1, const float* __restrict__ bd1,
    const float* __restrict__ Wd2,
    const float* __restrict__ WE,  const float* __restrict__ bE,
    const float* __restrict__ Wnu, const float* __restrict__ bnu,
    float* __restrict__ out)
{
    __shared__ SmemT S;

    const int tid  = threadIdx.x;
    const int wrp  = tid >> 5;
    const int lane = tid & 31;
    const int g    = lane >> 2;
    const int t4   = lane & 3;

    // ABG scratch aliased into STGE (init-only; exactly 1024 floats)
    float (*ABG)[4] = reinterpret_cast<float(*)[4]>(&S.STGE[0][0][0]);

    {   // derived per-h params: alpha, beta, gamma, 2c
        const int h = tid;
        const float* w1 = We1 + h * DIN;
        float a = be1[h], bt = 0.f, gm = 0.f;
#pragma unroll
        for (int k = 0; k < 16; ++k) { float w = w1[14 + k]; a += w * bE[k];  bt += w * WE[k]; }
#pragma unroll
        for (int k = 0; k < 16; ++k) { float w = w1[30 + k]; a += w * bnu[k]; gm += w * Wnu[k]; }
        ABG[0 * H + h][0] = a; ABG[0 * H + h][1] = bt; ABG[0 * H + h][2] = gm;
        ABG[0 * H + h][3] = 2.f * (We2[h] + We2[H + h]);
        ((float*)S.AP)[0 * H + h] = a;

        const float* w2 = Wd1 + h * DIN;
        a = bd1[h]; bt = 0.f; gm = 0.f;
#pragma unroll
        for (int k = 0; k < 16; ++k) { float w = w2[14 + k]; a += w * bE[k];  bt += w * WE[k]; }
#pragma unroll
        for (int k = 0; k < 16; ++k) { float w = w2[30 + k]; a += w * bnu[k]; gm += w * Wnu[k]; }
        ABG[1 * H + h][0] = a; ABG[1 * H + h][1] = bt; ABG[1 * H + h][2] = gm;
        ABG[1 * H + h][3] = 2.f * Wd2[h];
        ((float*)S.AP)[1 * H + h] = a;
    }
    __syncthreads();

    // GEMM1 W frags. X k-order: k0-7 = xi/−d slots (W cols 6..13); k8-13 = e/edot (W cols 0..5);
    // k14 = beta (E), k15 = gamma (nu).
    for (int it = tid; it < 2 * 16 * 32; it += 128) {
        int ln = it & 31, nt = (it >> 5) & 15, m = it >> 9;
        int gg = ln >> 2, tt = ln & 3, h = nt * 8 + gg;
        const float* W = (m ? Wd1 : We1) + h * DIN;
        int ks[4] = {2 * tt, 2 * tt + 1, 2 * tt + 8, 2 * tt + 9};
        uint16_t hb[4], lb[4];
#pragma unroll
        for (int i = 0; i < 4; ++i) {
            int k = ks[i];
            float v = (k < 8) ? W[6 + k]
                    : (k < 14) ? W[k - 8]
                    : (k == 14) ? ABG[m * H + h][1] : ABG[m * H + h][2];
            splits(v, hb[i], lb[i]);
        }
        S.BW[m][nt][ln] = make_uint4((uint32_t)hb[0] | ((uint32_t)hb[1] << 16),
                                     (uint32_t)hb[2] | ((uint32_t)hb[3] << 16),
                                     (uint32_t)lb[0] | ((uint32_t)lb[1] << 16),
                                     (uint32_t)lb[2] | ((uint32_t)lb[3] << 16));
    }
    // GEMM2 V frags. Output n-order: n0-7 = d/kin (W cols 6..13); n8-13 = s (W cols 0..5); n14,15 = 0.
    for (int it = tid; it < 2 * 8 * 2 * 32; it += 128) {
        int ln = it & 31, nt = (it >> 5) & 1, kt = (it >> 6) & 7, m = it >> 9;
        int gg = ln >> 2, tt = ln & 3, n = nt * 8 + gg;
        const float* W = m ? Wd1 : We1;
        int hs[4] = {kt * 16 + 2 * tt, kt * 16 + 2 * tt + 1,
                     kt * 16 + 2 * tt + 8, kt * 16 + 2 * tt + 9};
        uint16_t hb[4], lb[4];
#pragma unroll
        for (int i = 0; i < 4; ++i) {
            float v = 0.f;
            if (n < 14) {
                int c = (n < 8) ? 6 + n : n - 8;
                v = ABG[m * H + hs[i]][3] * W[hs[i] * DIN + c];
            }
            splits(v, hb[i], lb[i]);
        }
        S.BV[m][kt][nt][ln] = make_uint4((uint32_t)hb[0] | ((uint32_t)hb[1] << 16),
                                         (uint32_t)hb[2] | ((uint32_t)hb[3] << 16),
                                         (uint32_t)lb[0] | ((uint32_t)lb[1] << 16),
                                         (uint32_t)lb[2] | ((uint32_t)lb[3] << 16));
    }
    __syncthreads();   // also guards ABG (aliased into STGE) before stage use

    // ---- per-lane row ownership for inputs: lane owns row rb+lane ----
    const int rb = blockIdx.x * 128 + wrp * 32;
    const int br = rb + lane;
    const float* pe = e    + (size_t)br * TD;
    const float* pd = edot + (size_t)br * TD;
    uint32_t u3h, u3l;
    split2(Eg[br], nug[br], u3h, u3l);     // (E, nu) pre-split, loop-invariant

    // fragment-row output pointers (rows g, g+8, 16+g, 24+g)
    float* soR0 = out + (size_t)(rb + g) * TD;
    float* soR1 = soR0 + 8 * (size_t)TD;
    float* soR2 = soR0 + 16 * (size_t)TD;
    float* soR3 = soR0 + 24 * (size_t)TD;
    const size_t XOFF = (size_t)B_TOT * TD;
    float* xoR0 = out + XOFF + (size_t)(rb + g) * (T_LEN * NIV);
    float* xoR1 = xoR0 + 8 * (size_t)(T_LEN * NIV);
    float* xoR2 = xoR0 + 16 * (size_t)(T_LEN * NIV);
    float* xoR3 = xoR0 + 24 * (size_t)(T_LEN * NIV);

    uint2 (*stgE)[4] = S.STGE[wrp];
    uint2 (*stgD)[4] = S.STGD[wrp];

    // xi as register C-fragments (rows g,g+8 | 16+g,24+g; cols 2t4,2t4+1)
    float xsf0[4] = {0.f, 0.f, 0.f, 0.f}, xsf1[4] = {0.f, 0.f, 0.f, 0.f};

    float ce[6], cd[6];
#pragma unroll
    for (int j = 0; j < 6; ++j) { ce[j] = pe[j]; cd[j] = pd[j]; }

    for (int t = 0; t < T_LEN; ++t) {
        // xi out (state entering step), straight from fragments
        {
            int ox = t * NIV + 2 * t4;
            *(float2*)(xoR0 + ox) = make_float2(xsf0[0], xsf0[1]);
            *(float2*)(xoR1 + ox) = make_float2(xsf0[2], xsf0[3]);
            *(float2*)(xoR2 + ox) = make_float2(xsf1[0], xsf1[1]);
            *(float2*)(xoR3 + ox) = make_float2(xsf1[2], xsf1[3]);
        }

        // stage pre-split [e(6),E,nu] and [edot(6),E,nu] for this lane's row
        {
            uint32_t h0, l0, h1, l1, h2, l2;
            split2(ce[0], ce[1], h0, l0);
            split2(ce[2], ce[3], h1, l1);
            split2(ce[4], ce[5], h2, l2);
            *(uint4*)&stgE[lane][0] = make_uint4(h0, l0, h1, l1);
            *(uint4*)&stgE[lane][2] = make_uint4(h2, l2, u3h, u3l);
            split2(cd[0], cd[1], h0, l0);
            split2(cd[2], cd[3], h1, l1);
            split2(cd[4], cd[5], h2, l2);
            *(uint4*)&stgD[lane][0] = make_uint4(h0, l0, h1, l1);
            *(uint4*)&stgD[lane][2] = make_uint4(h2, l2, u3h, u3l);
        }
        __syncwarp();

        // prefetch next step inputs
        if (t + 1 < T_LEN) {
            const int o = (t + 1) * DE;
#pragma unroll
            for (int j = 0; j < 6; j += 2) {
                float2 v1 = *(const float2*)(pe + o + j); ce[j] = v1.x; ce[j + 1] = v1.y;
                float2 v2 = *(const float2*)(pd + o + j); cd[j] = v2.x; cd[j + 1] = v2.y;
            }
        }

        // ---- E-MLP: A k0-7 from xi frags, k8-15 from stgE ----
        uint32_t aH0[4], aL0[4], aH1[4], aL1[4];
        split2(xsf0[0], xsf0[1], aH0[0], aL0[0]);
        split2(xsf0[2], xsf0[3], aH0[1], aL0[1]);
        split2(xsf1[0], xsf1[1], aH1[0], aL1[0]);
        split2(xsf1[2], xsf1[3], aH1[1], aL1[1]);
        {
            uint2 q;
            q = stgE[g][t4];      aH0[2] = q.x; aL0[2] = q.y;
            q = stgE[g + 8][t4];  aH0[3] = q.x; aL0[3] = q.y;
            q = stgE[16 + g][t4]; aH1[2] = q.x; aL1[2] = q.y;
            q = stgE[24 + g][t4]; aH1[3] = q.x; aL1[3] = q.y;
        }
        float dE0[4], sE0[4], dE1[4], sE1[4];
        mlp_tc(&S, 0, lane, t4, aH0, aL0, aH1, aL1, dE0, sE0, dE1, sE1);

        // ---- D-MLP: A k0-7 = split(-d) direct from C-frags, k8-15 from stgD ----
        split2(-dE0[0], -dE0[1], aH0[0], aL0[0]);
        split2(-dE0[2], -dE0[3], aH0[1], aL0[1]);
        split2(-dE1[0], -dE1[1], aH1[0], aL1[0]);
        split2(-dE1[2], -dE1[3], aH1[1], aL1[1]);
        {
            uint2 q;
            q = stgD[g][t4];      aH0[2] = q.x; aL0[2] = q.y;
            q = stgD[g + 8][t4];  aH0[3] = q.x; aL0[3] = q.y;
            q = stgD[16 + g][t4]; aH1[2] = q.x; aL1[2] = q.y;
            q = stgD[24 + g][t4]; aH1[3] = q.x; aL1[3] = q.y;
        }
        float kin0[4], sn0[4], kin1[4], sn1[4];
        mlp_tc(&S, 1, lane, t4, aH0, aL0, aH1, aL1, kin0, sn0, kin1, sn1);

        // ---- epilogue: stress from fragments; xi frag update ----
        if (t4 < 3) {
            int oc = t * DE + 2 * t4;
            *(float2*)(soR0 + oc) = make_float2(sE0[0] - sn0[0], sE0[1] - sn0[1]);
            *(float2*)(soR1 + oc) = make_float2(sE0[2] - sn0[2], sE0[3] - sn0[3]);
            *(float2*)(soR2 + oc) = make_float2(sE1[0] - sn1[0], sE1[1] - sn1[1]);
            *(float2*)(soR3 + oc) = make_float2(sE1[2] - sn1[2], sE1[3] - sn1[3]);
        }
#pragma unroll
        for (int i = 0; i < 4; ++i) {
            xsf0[i] = fmaf(kin0[i], 0.01f, xsf0[i]);
            xsf1[i] = fmaf(kin1[i], 0.01f, xsf1[i]);
        }
        __syncwarp();   // stage arrays reused next step
    }
}

extern "C" void kernel_launch(void* const* d_in, const int* in_sizes, int n_in,
                              void* d_out, int out_size) {
    const float* e    = (const float*)d_in[0];
    const float* edot = (const float*)d_in[1];
    const float* Eg   = (const float*)d_in[2];
    const float* nug  = (const float*)d_in[3];
    const float* We1  = (const float*)d_in[4];
    const float* be1  = (const float*)d_in[5];
    const float* We2  = (const float*)d_in[6];
    const float* Wd1  = (const float*)d_in[8];
    const float* bd1  = (const float*)d_in[9];
    const float* Wd2  = (const float*)d_in[10];
    const float* WE   = (const float*)d_in[12];
    const float* bE   = (const float*)d_in[13];
    const float* Wnu  = (const float*)d_in[14];
    const float* bnu  = (const float*)d_in[15];
    float* out = (float*)d_out;

    visco_mma<<<NCTA, 128>>>(e, edot, Eg, nug, We1, be1, We2,
                             Wd1, bd1, Wd2, WE, bE, Wnu, bnu, out);
}

// round 15
// speedup vs baseline: 8.6512x; 1.0130x over previous
#include <cuda_runtime.h>
#include <cuda_bf16.h>
#include <cstdint>

#define B_TOT 32768
#define T_LEN 200
#define DE    6
#define NIV   8
#define H     128
#define DIN   46
#define TD    (T_LEN*DE)
#define NCTA  (B_TOT/64)     // 512 blocks, 4 warps x 16 rows

struct SmemT {
    uint4  BW[2][16][32];       // [mlp][ntile][lane]: (hi.x,hi.y,lo.x,lo.y) GEMM1 W frags
    uint4  BV[2][8][2][32];     // [mlp][ktile][ntile][lane] GEMM2 V frags
    float2 AP[2][64];           // alpha pairs
    uint2  STGE[4][16][4];      // per-warp: pre-split [e(6),E,nu] (hi,lo) pairs
    uint2  STGD[4][16][4];      // per-warp: pre-split [edot(6),E,nu]
};

static __device__ __forceinline__ void mma16816(float c[4], const uint32_t a[4], uint2 b) {
    asm volatile("mma.sync.aligned.m16n8k16.row.col.f32.bf16.bf16.f32 "
        "{%0,%1,%2,%3}, {%4,%5,%6,%7}, {%8,%9}, {%0,%1,%2,%3};"
        : "+f"(c[0]), "+f"(c[1]), "+f"(c[2]), "+f"(c[3])
        : "r"(a[0]), "r"(a[1]), "r"(a[2]), "r"(a[3]), "r"(b.x), "r"(b.y));
}
static __device__ __forceinline__ uint32_t cvt2(float even, float odd) {
    uint32_t r;
    asm("cvt.rn.bf16x2.f32 %0, %1, %2;" : "=r"(r) : "f"(odd), "f"(even));
    return r;
}
static __device__ __forceinline__ void split2(float even, float odd, uint32_t& hi, uint32_t& lo) {
    hi = cvt2(even, odd);
    float he = __uint_as_float(hi << 16);
    float ho = __uint_as_float(hi & 0xFFFF0000u);
    lo = cvt2(even - he, odd - ho);
}
static __device__ __forceinline__ void splits(float v, uint16_t& hb, uint16_t& lb) {
    __nv_bfloat16 h = __float2bfloat16(v);
    hb = __bfloat16_as_ushort(h);
    lb = __bfloat16_as_ushort(__float2bfloat16(v - __bfloat162float(h)));
}

// Fused MLP (GEMM1 j-tile -> relu/split -> GEMM2 kt=j) for one 16-row m-tile.
// Outputs: dT = n-tile0 (d / kinetics cols), sT = n-tile1 (stress cols).
static __device__ __forceinline__ void mlp_tc(
    const SmemT* __restrict__ S, int m, int lane, int t4,
    const uint32_t aH[4], const uint32_t aL[4],
    float dT[4], float sT[4])
{
#pragma unroll
    for (int i = 0; i < 4; ++i) { dT[i] = 0.f; sT[i] = 0.f; }
#pragma unroll
    for (int j = 0; j < 8; ++j) {
        uint4 w0 = S->BW[m][2 * j][lane];
        uint4 w1 = S->BW[m][2 * j + 1][lane];
        float2 A0 = S->AP[m][8 * j + t4];
        float2 A1 = S->AP[m][8 * j + 4 + t4];
        uint2 w0h = make_uint2(w0.x, w0.y), w0l = make_uint2(w0.z, w0.w);
        uint2 w1h = make_uint2(w1.x, w1.y), w1l = make_uint2(w1.z, w1.w);

        float c0[4] = {0.f,0.f,0.f,0.f}, c1[4] = {0.f,0.f,0.f,0.f};
        mma16816(c0, aH, w0h); mma16816(c0, aH, w0l); mma16816(c0, aL, w0h);
        mma16816(c1, aH, w1h); mma16816(c1, aH, w1l); mma16816(c1, aL, w1h);

        c0[0] = fmaxf(c0[0] + A0.x, 0.f); c0[1] = fmaxf(c0[1] + A0.y, 0.f);
        c0[2] = fmaxf(c0[2] + A0.x, 0.f); c0[3] = fmaxf(c0[3] + A0.y, 0.f);
        c1[0] = fmaxf(c1[0] + A1.x, 0.f); c1[1] = fmaxf(c1[1] + A1.y, 0.f);
        c1[2] = fmaxf(c1[2] + A1.x, 0.f); c1[3] = fmaxf(c1[3] + A1.y, 0.f);

        uint32_t RAh[4], RAl[4];
        split2(c0[0], c0[1], RAh[0], RAl[0]);
        split2(c0[2], c0[3], RAh[1], RAl[1]);
        split2(c1[0], c1[1], RAh[2], RAl[2]);
        split2(c1[2], c1[3], RAh[3], RAl[3]);

        uint4 v0 = S->BV[m][j][0][lane];
        uint4 v1 = S->BV[m][j][1][lane];
        uint2 v0h = make_uint2(v0.x, v0.y), v0l = make_uint2(v0.z, v0.w);
        uint2 v1h = make_uint2(v1.x, v1.y), v1l = make_uint2(v1.z, v1.w);
        mma16816(dT, RAh, v0h); mma16816(dT, RAh, v0l); mma16816(dT, RAl, v0h);
        mma16816(sT, RAh, v1h); mma16816(sT, RAh, v1l); mma16816(sT, RAl, v1h);
    }
}

__global__ void __launch_bounds__(128, 4) visco_mma(
    const float* __restrict__ e,   const float* __restrict__ edot,
    const float* __restrict__ Eg,  const float* __restrict__ nug,
    const float* __restrict__ We1, const float* __restrict__ be1,
    const float* __restrict__ We2,
    const float* __restrict__ Wd1, const float* __restrict__ bd1,
    const float* __restrict__ Wd2,
    const float* __restrict__ WE,  const float* __restrict__ bE,
    const float* __restrict__ Wnu, const float* __restrict__ bnu,
    float* __restrict__ out)
{
    __shared__ SmemT S;

    const int tid  = threadIdx.x;
    const int wrp  = tid >> 5;
    const int lane = tid & 31;
    const int g    = lane >> 2;
    const int t4   = lane & 3;

    // ABG scratch aliased into STGE+STGD (init-only; exactly 4KB = 1024 floats)
    float (*ABG)[4] = reinterpret_cast<float(*)[4]>(&S.STGE[0][0][0]);

    {   // derived per-h params: alpha, beta, gamma, 2c
        const int h = tid;
        const float* w1 = We1 + h * DIN;
        float a = be1[h], bt = 0.f, gm = 0.f;
#pragma unroll
        for (int k = 0; k < 16; ++k) { float w = w1[14 + k]; a += w * bE[k];  bt += w * WE[k]; }
#pragma unroll
        for (int k = 0; k < 16; ++k) { float w = w1[30 + k]; a += w * bnu[k]; gm += w * Wnu[k]; }
        ABG[0 * H + h][0] = a; ABG[0 * H + h][1] = bt; ABG[0 * H + h][2] = gm;
        ABG[0 * H + h][3] = 2.f * (We2[h] + We2[H + h]);
        ((float*)S.AP)[0 * H + h] = a;

        const float* w2 = Wd1 + h * DIN;
        a = bd1[h]; bt = 0.f; gm = 0.f;
#pragma unroll
        for (int k = 0; k < 16; ++k) { float w = w2[14 + k]; a += w * bE[k];  bt += w * WE[k]; }
#pragma unroll
        for (int k = 0; k < 16; ++k) { float w = w2[30 + k]; a += w * bnu[k]; gm += w * Wnu[k]; }
        ABG[1 * H + h][0] = a; ABG[1 * H + h][1] = bt; ABG[1 * H + h][2] = gm;
        ABG[1 * H + h][3] = 2.f * Wd2[h];
        ((float*)S.AP)[1 * H + h] = a;
    }
    __syncthreads();

    // GEMM1 W frags. X k-order: k0-7 = xi/−d (W cols 6..13); k8-13 = e/edot (W cols 0..5);
    // k14 = beta (E), k15 = gamma (nu).
    for (int it = tid; it < 2 * 16 * 32; it += 128) {
        int ln = it & 31, nt = (it >> 5) & 15, m = it >> 9;
        int gg = ln >> 2, tt = ln & 3, h = nt * 8 + gg;
        const float* W = (m ? Wd1 : We1) + h * DIN;
        int ks[4] = {2 * tt, 2 * tt + 1, 2 * tt + 8, 2 * tt + 9};
        uint16_t hb[4], lb[4];
#pragma unroll
        for (int i = 0; i < 4; ++i) {
            int k = ks[i];
            float v = (k < 8) ? W[6 + k]
                    : (k < 14) ? W[k - 8]
                    : (k == 14) ? ABG[m * H + h][1] : ABG[m * H + h][2];
            splits(v, hb[i], lb[i]);
        }
        S.BW[m][nt][ln] = make_uint4((uint32_t)hb[0] | ((uint32_t)hb[1] << 16),
                                     (uint32_t)hb[2] | ((uint32_t)hb[3] << 16),
                                     (uint32_t)lb[0] | ((uint32_t)lb[1] << 16),
                                     (uint32_t)lb[2] | ((uint32_t)lb[3] << 16));
    }
    // GEMM2 V frags. Output n-order: n0-7 = d/kin (W cols 6..13); n8-13 = s (W cols 0..5); n14,15 = 0.
    for (int it = tid; it < 2 * 8 * 2 * 32; it += 128) {
        int ln = it & 31, nt = (it >> 5) & 1, kt = (it >> 6) & 7, m = it >> 9;
        int gg = ln >> 2, tt = ln & 3, n = nt * 8 + gg;
        const float* W = m ? Wd1 : We1;
        int hs[4] = {kt * 16 + 2 * tt, kt * 16 + 2 * tt + 1,
                     kt * 16 + 2 * tt + 8, kt * 16 + 2 * tt + 9};
        uint16_t hb[4], lb[4];
#pragma unroll
        for (int i = 0; i < 4; ++i) {
            float v = 0.f;
            if (n < 14) {
                int c = (n < 8) ? 6 + n : n - 8;
                v = ABG[m * H + hs[i]][3] * W[hs[i] * DIN + c];
            }
            splits(v, hb[i], lb[i]);
        }
        S.BV[m][kt][nt][ln] = make_uint4((uint32_t)hb[0] | ((uint32_t)hb[1] << 16),
                                         (uint32_t)hb[2] | ((uint32_t)hb[3] << 16),
                                         (uint32_t)lb[0] | ((uint32_t)lb[1] << 16),
                                         (uint32_t)lb[2] | ((uint32_t)lb[3] << 16));
    }
    __syncthreads();   // guards ABG (aliased into staging) before stage use

    // ---- warp owns 16 rows; lane < 16 owns one input row ----
    const int rb = blockIdx.x * 64 + wrp * 16;
    const bool own = (lane < 16);
    const int br = rb + (lane & 15);
    const float* pe = e    + (size_t)br * TD;
    const float* pd = edot + (size_t)br * TD;

    uint2 (*stgE)[4] = S.STGE[wrp];
    uint2 (*stgD)[4] = S.STGD[wrp];

    // loop-invariant (E, nu) pre-split, staged once
    if (own) {
        uint32_t u3h, u3l;
        split2(Eg[br], nug[br], u3h, u3l);
        stgE[lane][3] = make_uint2(u3h, u3l);
        stgD[lane][3] = make_uint2(u3h, u3l);
    }

    // fragment-row output pointers (rows g, g+8)
    float* soR0 = out + (size_t)(rb + g) * TD;
    float* soR1 = soR0 + 8 * (size_t)TD;
    const size_t XOFF = (size_t)B_TOT * TD;
    float* xoR0 = out + XOFF + (size_t)(rb + g) * (T_LEN * NIV);
    float* xoR1 = xoR0 + 8 * (size_t)(T_LEN * NIV);

    // xi as register C-fragment (rows g, g+8; cols 2t4, 2t4+1)
    float xsf[4] = {0.f, 0.f, 0.f, 0.f};

    float ce[6], cd[6];
    if (own) {
#pragma unroll
        for (int j = 0; j < 6; ++j) { ce[j] = pe[j]; cd[j] = pd[j]; }
    }
    __syncwarp();

    for (int t = 0; t < T_LEN; ++t) {
        // xi out (state entering step), straight from fragments
        {
            int ox = t * NIV + 2 * t4;
            *(float2*)(xoR0 + ox) = make_float2(xsf[0], xsf[1]);
            *(float2*)(xoR1 + ox) = make_float2(xsf[2], xsf[3]);
        }

        // stage pre-split [e(6)] and [edot(6)] for this lane's row
        if (own) {
            uint32_t h0, l0, h1, l1, h2, l2;
            split2(ce[0], ce[1], h0, l0);
            split2(ce[2], ce[3], h1, l1);
            split2(ce[4], ce[5], h2, l2);
            *(uint4*)&stgE[lane][0] = make_uint4(h0, l0, h1, l1);
            stgE[lane][2] = make_uint2(h2, l2);
            split2(cd[0], cd[1], h0, l0);
            split2(cd[2], cd[3], h1, l1);
            split2(cd[4], cd[5], h2, l2);
            *(uint4*)&stgD[lane][0] = make_uint4(h0, l0, h1, l1);
            stgD[lane][2] = make_uint2(h2, l2);
        }
        __syncwarp();

        // prefetch next step inputs
        if (own && t + 1 < T_LEN) {
            const int o = (t + 1) * DE;
#pragma unroll
            for (int j = 0; j < 6; j += 2) {
                float2 v1 = *(const float2*)(pe + o + j); ce[j] = v1.x; ce[j + 1] = v1.y;
                float2 v2 = *(const float2*)(pd + o + j); cd[j] = v2.x; cd[j + 1] = v2.y;
            }
        }

        // ---- E-MLP: A k0-7 from xi frags, k8-15 from stgE ----
        uint32_t aH[4], aL[4];
        split2(xsf[0], xsf[1], aH[0], aL[0]);
        split2(xsf[2], xsf[3], aH[1], aL[1]);
        {
            uint2 q;
            q = stgE[g][t4];     aH[2] = q.x; aL[2] = q.y;
            q = stgE[g + 8][t4]; aH[3] = q.x; aL[3] = q.y;
        }
        float dE[4], sE[4];
        mlp_tc(&S, 0, lane, t4, aH, aL, dE, sE);

        // ---- D-MLP: A k0-7 = split(-d) direct from C-frags, k8-15 from stgD ----
        split2(-dE[0], -dE[1], aH[0], aL[0]);
        split2(-dE[2], -dE[3], aH[1], aL[1]);
        {
            uint2 q;
            q = stgD[g][t4];     aH[2] = q.x; aL[2] = q.y;
            q = stgD[g + 8][t4]; aH[3] = q.x; aL[3] = q.y;
        }
        float kin[4], sn[4];
        mlp_tc(&S, 1, lane, t4, aH, aL, kin, sn);

        // ---- epilogue: stress from fragments; xi frag update ----
        if (t4 < 3) {
            int oc = t * DE + 2 * t4;
            *(float2*)(soR0 + oc) = make_float2(sE[0] - sn[0], sE[1] - sn[1]);
            *(float2*)(soR1 + oc) = make_float2(sE[2] - sn[2], sE[3] - sn[3]);
        }
#pragma unroll
        for (int i = 0; i < 4; ++i)
            xsf[i] = fmaf(kin[i], 0.01f, xsf[i]);
        __syncwarp();   // stage arrays reused next step
    }
}

extern "C" void kernel_launch(void* const* d_in, const int* in_sizes, int n_in,
                              void* d_out, int out_size) {
    const float* e    = (const float*)d_in[0];
    const float* edot = (const float*)d_in[1];
    const float* Eg   = (const float*)d_in[2];
    const float* nug  = (const float*)d_in[3];
    const float* We1  = (const float*)d_in[4];
    const float* be1  = (const float*)d_in[5];
    const float* We2  = (const float*)d_in[6];
    const float* Wd1  = (const float*)d_in[8];
    const float* bd1  = (const float*)d_in[9];
    const float* Wd2  = (const float*)d_in[10];
    const float* WE   = (const float*)d_in[12];
    const float* bE   = (const float*)d_in[13];
    const float* Wnu  = (const float*)d_in[14];
    const float* bnu  = (const float*)d_in[15];
    float* out = (float*)d_out;

    visco_mma<<<NCTA, 128>>>(e, edot, Eg, nug, We1, be1, We2,
                             Wd1, bd1, Wd2, WE, bE, Wnu, bnu, out);
}

// round 16
// speedup vs baseline: 11.3099x; 1.3073x over previous
#include <cuda_runtime.h>
#include <cuda_fp16.h>
#include <cstdint>

#define B_TOT 32768
#define T_LEN 200
#define DE    6
#define NIV   8
#define H     128
#define DIN   46
#define TD    (T_LEN*DE)
#define NCTA  (B_TOT/64)     // 512 blocks, 4 warps x 16 rows

struct SmemT {
    uint4    BW[2][16][32];      // [mlp][ntile][lane]: (hi.x,hi.y,lo.x,lo.w) GEMM1 W frags (fp16)
    uint4    BV[2][8][2][32];    // [mlp][ktile][ntile][lane] GEMM2 V frags (fp16)
    float2   AP[2][64];          // alpha pairs (fp32 bias)
    uint32_t STGE[4][16][4];     // per-warp: fp16-pair staging [e(6),E,nu]
    uint32_t STGD[4][16][4];     // per-warp: fp16-pair staging [edot(6),E,nu]
    float    ABG[2 * H][4];      // init scratch: alpha, beta, gamma, 2c
};

// ---- m16n8k16 fp16 MMA, fp32 accumulate in place ----
static __device__ __forceinline__ void mma16816(float c[4], const uint32_t a[4], uint2 b) {
    asm volatile("mma.sync.aligned.m16n8k16.row.col.f32.f16.f16.f32 "
        "{%0,%1,%2,%3}, {%4,%5,%6,%7}, {%8,%9}, {%0,%1,%2,%3};"
        : "+f"(c[0]), "+f"(c[1]), "+f"(c[2]), "+f"(c[3])
        : "r"(a[0]), "r"(a[1]), "r"(a[2]), "r"(a[3]), "r"(b.x), "r"(b.y));
}
// pack (even, odd) -> fp16x2, even in LOW half
static __device__ __forceinline__ uint32_t pkh2(float even, float odd) {
    uint32_t r;
    asm("cvt.rn.f16x2.f32 %0, %1, %2;" : "=r"(r) : "f"(odd), "f"(even));
    return r;
}
// scalar fp16 split (B-side only): hi + residual lo
static __device__ __forceinline__ void splits(float v, uint16_t& hb, uint16_t& lb) {
    __half h = __float2half_rn(v);
    hb = __half_as_ushort(h);
    lb = __half_as_ushort(__float2half_rn(v - __half2float(h)));
}

// Fused MLP: GEMM1 j-tile (2-pass B-split) -> bias+relu -> fp16 -> GEMM2 kt=j (2-pass).
// dT = n-tile0 C-frag (d / kinetics cols), sT = n-tile1 (stress cols).
static __device__ __forceinline__ void mlp_tc(
    const SmemT* __restrict__ S, int m, int lane, int t4,
    const uint32_t aF[4], float dT[4], float sT[4])
{
#pragma unroll
    for (int i = 0; i < 4; ++i) { dT[i] = 0.f; sT[i] = 0.f; }
#pragma unroll
    for (int j = 0; j < 8; ++j) {
        uint4 w0 = S->BW[m][2 * j][lane];
        uint4 w1 = S->BW[m][2 * j + 1][lane];
        float2 A0 = S->AP[m][8 * j + t4];
        float2 A1 = S->AP[m][8 * j + 4 + t4];

        float c0[4] = {0.f,0.f,0.f,0.f}, c1[4] = {0.f,0.f,0.f,0.f};
        mma16816(c0, aF, make_uint2(w0.x, w0.y));
        mma16816(c0, aF, make_uint2(w0.z, w0.w));
        mma16816(c1, aF, make_uint2(w1.x, w1.y));
        mma16816(c1, aF, make_uint2(w1.z, w1.w));

        c0[0] = fmaxf(c0[0] + A0.x, 0.f); c0[1] = fmaxf(c0[1] + A0.y, 0.f);
        c0[2] = fmaxf(c0[2] + A0.x, 0.f); c0[3] = fmaxf(c0[3] + A0.y, 0.f);
        c1[0] = fmaxf(c1[0] + A1.x, 0.f); c1[1] = fmaxf(c1[1] + A1.y, 0.f);
        c1[2] = fmaxf(c1[2] + A1.x, 0.f); c1[3] = fmaxf(c1[3] + A1.y, 0.f);

        uint32_t RF[4];
        RF[0] = pkh2(c0[0], c0[1]);
        RF[1] = pkh2(c0[2], c0[3]);
        RF[2] = pkh2(c1[0], c1[1]);
        RF[3] = pkh2(c1[2], c1[3]);

        uint4 v0 = S->BV[m][j][0][lane];
        uint4 v1 = S->BV[m][j][1][lane];
        mma16816(dT, RF, make_uint2(v0.x, v0.y));
        mma16816(dT, RF, make_uint2(v0.z, v0.w));
        mma16816(sT, RF, make_uint2(v1.x, v1.y));
        mma16816(sT, RF, make_uint2(v1.z, v1.w));
    }
}

__global__ void __launch_bounds__(128, 4) visco_mma(
    const float* __restrict__ e,   const float* __restrict__ edot,
    const float* __restrict__ Eg,  const float* __restrict__ nug,
    const float* __restrict__ We1, const float* __restrict__ be1,
    const float* __restrict__ We2,
    const float* __restrict__ Wd1, const float* __restrict__ bd1,
    const float* __restrict__ Wd2,
    const float* __restrict__ WE,  const float* __restrict__ bE,
    const float* __restrict__ Wnu, const float* __restrict__ bnu,
    float* __restrict__ out)
{
    __shared__ SmemT S;

    const int tid  = threadIdx.x;
    const int wrp  = tid >> 5;
    const int lane = tid & 31;
    const int g    = lane >> 2;
    const int t4   = lane & 3;

    {   // derived per-h params: alpha, beta, gamma, 2c
        const int h = tid;
        const float* w1 = We1 + h * DIN;
        float a = be1[h], bt = 0.f, gm = 0.f;
#pragma unroll
        for (int k = 0; k < 16; ++k) { float w = w1[14 + k]; a += w * bE[k];  bt += w * WE[k]; }
#pragma unroll
        for (int k = 0; k < 16; ++k) { float w = w1[30 + k]; a += w * bnu[k]; gm += w * Wnu[k]; }
        S.ABG[0 * H + h][0] = a; S.ABG[0 * H + h][1] = bt; S.ABG[0 * H + h][2] = gm;
        S.ABG[0 * H + h][3] = 2.f * (We2[h] + We2[H + h]);
        ((float*)S.AP)[0 * H + h] = a;

        const float* w2 = Wd1 + h * DIN;
        a = bd1[h]; bt = 0.f; gm = 0.f;
#pragma unroll
        for (int k = 0; k < 16; ++k) { float w = w2[14 + k]; a += w * bE[k];  bt += w * WE[k]; }
#pragma unroll
        for (int k = 0; k < 16; ++k) { float w = w2[30 + k]; a += w * bnu[k]; gm += w * Wnu[k]; }
        S.ABG[1 * H + h][0] = a; S.ABG[1 * H + h][1] = bt; S.ABG[1 * H + h][2] = gm;
        S.ABG[1 * H + h][3] = 2.f * Wd2[h];
        ((float*)S.AP)[1 * H + h] = a;
    }
    __syncthreads();

    // GEMM1 W frags. X k-order: k0-7 = xi/−d (W cols 6..13); k8-13 = e/edot (W cols 0..5);
    // k14 = beta (E), k15 = gamma (nu).
    for (int it = tid; it < 2 * 16 * 32; it += 128) {
        int ln = it & 31, nt = (it >> 5) & 15, m = it >> 9;
        int gg = ln >> 2, tt = ln & 3, h = nt * 8 + gg;
        const float* W = (m ? Wd1 : We1) + h * DIN;
        int ks[4] = {2 * tt, 2 * tt + 1, 2 * tt + 8, 2 * tt + 9};
        uint16_t hb[4], lb[4];
#pragma unroll
        for (int i = 0; i < 4; ++i) {
            int k = ks[i];
            float v = (k < 8) ? W[6 + k]
                    : (k < 14) ? W[k - 8]
                    : (k == 14) ? S.ABG[m * H + h][1] : S.ABG[m * H + h][2];
            splits(v, hb[i], lb[i]);
        }
        S.BW[m][nt][ln] = make_uint4((uint32_t)hb[0] | ((uint32_t)hb[1] << 16),
                                     (uint32_t)hb[2] | ((uint32_t)hb[3] << 16),
                                     (uint32_t)lb[0] | ((uint32_t)lb[1] << 16),
                                     (uint32_t)lb[2] | ((uint32_t)lb[3] << 16));
    }
    // GEMM2 V frags. Output n-order: n0-7 = d/kin (W cols 6..13); n8-13 = s (W cols 0..5); n14,15 = 0.
    for (int it = tid; it < 2 * 8 * 2 * 32; it += 128) {
        int ln = it & 31, nt = (it >> 5) & 1, kt = (it >> 6) & 7, m = it >> 9;
        int gg = ln >> 2, tt = ln & 3, n = nt * 8 + gg;
        const float* W = m ? Wd1 : We1;
        int hs[4] = {kt * 16 + 2 * tt, kt * 16 + 2 * tt + 1,
                     kt * 16 + 2 * tt + 8, kt * 16 + 2 * tt + 9};
        uint16_t hb[4], lb[4];
#pragma unroll
        for (int i = 0; i < 4; ++i) {
            float v = 0.f;
            if (n < 14) {
                int c = (n < 8) ? 6 + n : n - 8;
                v = S.ABG[m * H + hs[i]][3] * W[hs[i] * DIN + c];
            }
            splits(v, hb[i], lb[i]);
        }
        S.BV[m][kt][nt][ln] = make_uint4((uint32_t)hb[0] | ((uint32_t)hb[1] << 16),
                                         (uint32_t)hb[2] | ((uint32_t)hb[3] << 16),
                                         (uint32_t)lb[0] | ((uint32_t)lb[1] << 16),
                                         (uint32_t)lb[2] | ((uint32_t)lb[3] << 16));
    }
    __syncthreads();

    // ---- warp owns 16 rows; lane < 16 owns one input row ----
    const int rb = blockIdx.x * 64 + wrp * 16;
    const bool own = (lane < 16);
    const int br = rb + (lane & 15);
    const float* pe = e    + (size_t)br * TD;
    const float* pd = edot + (size_t)br * TD;

    uint32_t (*stgE)[4] = S.STGE[wrp];
    uint32_t (*stgD)[4] = S.STGD[wrp];

    // loop-invariant (E, nu) fp16 pair, staged once
    if (own) {
        uint32_t u3 = pkh2(Eg[br], nug[br]);
        stgE[lane][3] = u3;
        stgD[lane][3] = u3;
    }

    // fragment-row output pointers (rows g, g+8)
    float* soR0 = out + (size_t)(rb + g) * TD;
    float* soR1 = soR0 + 8 * (size_t)TD;
    const size_t XOFF = (size_t)B_TOT * TD;
    float* xoR0 = out + XOFF + (size_t)(rb + g) * (T_LEN * NIV);
    float* xoR1 = xoR0 + 8 * (size_t)(T_LEN * NIV);

    // xi as register C-fragment (rows g, g+8; cols 2t4, 2t4+1)
    float xsf[4] = {0.f, 0.f, 0.f, 0.f};

    float ce[6], cd[6];
    if (own) {
#pragma unroll
        for (int j = 0; j < 6; ++j) { ce[j] = pe[j]; cd[j] = pd[j]; }
    }
    __syncwarp();

    for (int t = 0; t < T_LEN; ++t) {
        // xi out (state entering step), straight from fragments
        {
            int ox = t * NIV + 2 * t4;
            *(float2*)(xoR0 + ox) = make_float2(xsf[0], xsf[1]);
            *(float2*)(xoR1 + ox) = make_float2(xsf[2], xsf[3]);
        }

        // stage fp16 pairs for [e(6)] / [edot(6)]
        if (own) {
            *(uint2*)&stgE[lane][0] = make_uint2(pkh2(ce[0], ce[1]), pkh2(ce[2], ce[3]));
            stgE[lane][2] = pkh2(ce[4], ce[5]);
            *(uint2*)&stgD[lane][0] = make_uint2(pkh2(cd[0], cd[1]), pkh2(cd[2], cd[3]));
            stgD[lane][2] = pkh2(cd[4], cd[5]);
        }
        __syncwarp();

        // prefetch next step inputs
        if (own && t + 1 < T_LEN) {
            const int o = (t + 1) * DE;
#pragma unroll
            for (int j = 0; j < 6; j += 2) {
                float2 v1 = *(const float2*)(pe + o + j); ce[j] = v1.x; ce[j + 1] = v1.y;
                float2 v2 = *(const float2*)(pd + o + j); cd[j] = v2.x; cd[j + 1] = v2.y;
            }
        }

        // ---- E-MLP: A k0-7 from xi frags (single fp16), k8-15 from stgE ----
        uint32_t aF[4];
        aF[0] = pkh2(xsf[0], xsf[1]);
        aF[1] = pkh2(xsf[2], xsf[3]);
        aF[2] = stgE[g][t4];
        aF[3] = stgE[g + 8][t4];
        float dE[4], sE[4];
        mlp_tc(&S, 0, lane, t4, aF, dE, sE);

        // ---- D-MLP: A k0-7 = -d direct from C-frags, k8-15 from stgD ----
        aF[0] = pkh2(-dE[0], -dE[1]);
        aF[1] = pkh2(-dE[2], -dE[3]);
        aF[2] = stgD[g][t4];
        aF[3] = stgD[g + 8][t4];
        float kin[4], sn[4];
        mlp_tc(&S, 1, lane, t4, aF, kin, sn);

        // ---- epilogue: stress from fragments; xi frag update ----
        if (t4 < 3) {
            int oc = t * DE + 2 * t4;
            *(float2*)(soR0 + oc) = make_float2(sE[0] - sn[0], sE[1] - sn[1]);
            *(float2*)(soR1 + oc) = make_float2(sE[2] - sn[2], sE[3] - sn[3]);
        }
#pragma unroll
        for (int i = 0; i < 4; ++i)
            xsf[i] = fmaf(kin[i], 0.01f, xsf[i]);
        __syncwarp();   // stage arrays reused next step
    }
}

extern "C" void kernel_launch(void* const* d_in, const int* in_sizes, int n_in,
                              void* d_out, int out_size) {
    const float* e    = (const float*)d_in[0];
    const float* edot = (const float*)d_in[1];
    const float* Eg   = (const float*)d_in[2];
    const float* nug  = (const float*)d_in[3];
    const float* We1  = (const float*)d_in[4];
    const float* be1  = (const float*)d_in[5];
    const float* We2  = (const float*)d_in[6];
    const float* Wd1  = (const float*)d_in[8];
    const float* bd1  = (const float*)d_in[9];
    const float* Wd2  = (const float*)d_in[10];
    const float* WE   = (const float*)d_in[12];
    const float* bE   = (const float*)d_in[13];
    const float* Wnu  = (const float*)d_in[14];
    const float* bnu  = (const float*)d_in[15];
    float* out = (float*)d_out;

    visco_mma<<<NCTA, 128>>>(e, edot, Eg, nug, We1, be1, We2,
                             Wd1, bd1, Wd2, WE, bE, Wnu, bnu, out);
}

// round 17
// speedup vs baseline: 13.6469x; 1.2066x over previous
#include <cuda_runtime.h>
#include <cuda_fp16.h>
#include <cstdint>

#define B_TOT 32768
#define T_LEN 200
#define DE    6
#define NIV   8
#define H     128
#define DIN   46
#define TD    (T_LEN*DE)
#define NCTA  (B_TOT/128)     // 256 blocks, 4 warps x 32 rows

struct SmemT {
    uint4    BW[2][16][32];      // [mlp][ntile][lane] GEMM1 W frags (fp16 hi|lo)
    uint4    BV[2][8][2][32];    // [mlp][ktile][ntile][lane] GEMM2 V frags
    float2   AP[2][64];          // alpha pairs (fp32 bias)
    uint32_t STGE[4][32][4];     // per-warp fp16-pair staging [e(6),E,nu]
    uint32_t STGD[4][32][4];     // per-warp fp16-pair staging [edot(6),E,nu]
    float    ABG[2 * H][4];      // init scratch
};

static __device__ __forceinline__ void mma16816(float c[4], const uint32_t a[4], uint2 b) {
    asm volatile("mma.sync.aligned.m16n8k16.row.col.f32.f16.f16.f32 "
        "{%0,%1,%2,%3}, {%4,%5,%6,%7}, {%8,%9}, {%0,%1,%2,%3};"
        : "+f"(c[0]), "+f"(c[1]), "+f"(c[2]), "+f"(c[3])
        : "r"(a[0]), "r"(a[1]), "r"(a[2]), "r"(a[3]), "r"(b.x), "r"(b.y));
}
static __device__ __forceinline__ uint32_t pkh2(float even, float odd) {
    uint32_t r;
    asm("cvt.rn.f16x2.f32 %0, %1, %2;" : "=r"(r) : "f"(odd), "f"(even));
    return r;
}
static __device__ __forceinline__ void splits(float v, uint16_t& hb, uint16_t& lb) {
    __half h = __float2half_rn(v);
    hb = __half_as_ushort(h);
    lb = __half_as_ushort(__float2half_rn(v - __half2float(h)));
}

// Fused MLP for TWO 16-row m-tiles: GEMM1 j-tile -> bias+relu -> fp16 -> GEMM2 kt=j.
// B fragments loaded once per j, shared by both m-tiles.
static __device__ __forceinline__ void mlp_tc(
    const SmemT* __restrict__ S, int m, int lane, int t4,
    const uint32_t aF0[4], const uint32_t aF1[4],
    float dT0[4], float sT0[4], float dT1[4], float sT1[4])
{
#pragma unroll
    for (int i = 0; i < 4; ++i) { dT0[i] = 0.f; sT0[i] = 0.f; dT1[i] = 0.f; sT1[i] = 0.f; }
#pragma unroll
    for (int j = 0; j < 8; ++j) {
        uint4 w0 = S->BW[m][2 * j][lane];
        uint4 w1 = S->BW[m][2 * j + 1][lane];
        float2 A0 = S->AP[m][8 * j + t4];
        float2 A1 = S->AP[m][8 * j + 4 + t4];
        uint2 w0h = make_uint2(w0.x, w0.y), w0l = make_uint2(w0.z, w0.w);
        uint2 w1h = make_uint2(w1.x, w1.y), w1l = make_uint2(w1.z, w1.w);

        float c0[4] = {0.f,0.f,0.f,0.f}, c1[4] = {0.f,0.f,0.f,0.f};
        float f0[4] = {0.f,0.f,0.f,0.f}, f1[4] = {0.f,0.f,0.f,0.f};
        mma16816(c0, aF0, w0h); mma16816(c0, aF0, w0l);
        mma16816(c1, aF0, w1h); mma16816(c1, aF0, w1l);
        mma16816(f0, aF1, w0h); mma16816(f0, aF1, w0l);
        mma16816(f1, aF1, w1h); mma16816(f1, aF1, w1l);

        c0[0] = fmaxf(c0[0] + A0.x, 0.f); c0[1] = fmaxf(c0[1] + A0.y, 0.f);
        c0[2] = fmaxf(c0[2] + A0.x, 0.f); c0[3] = fmaxf(c0[3] + A0.y, 0.f);
        c1[0] = fmaxf(c1[0] + A1.x, 0.f); c1[1] = fmaxf(c1[1] + A1.y, 0.f);
        c1[2] = fmaxf(c1[2] + A1.x, 0.f); c1[3] = fmaxf(c1[3] + A1.y, 0.f);
        f0[0] = fmaxf(f0[0] + A0.x, 0.f); f0[1] = fmaxf(f0[1] + A0.y, 0.f);
        f0[2] = fmaxf(f0[2] + A0.x, 0.f); f0[3] = fmaxf(f0[3] + A0.y, 0.f);
        f1[0] = fmaxf(f1[0] + A1.x, 0.f); f1[1] = fmaxf(f1[1] + A1.y, 0.f);
        f1[2] = fmaxf(f1[2] + A1.x, 0.f); f1[3] = fmaxf(f1[3] + A1.y, 0.f);

        uint32_t RF0[4], RF1[4];
        RF0[0] = pkh2(c0[0], c0[1]); RF0[1] = pkh2(c0[2], c0[3]);
        RF0[2] = pkh2(c1[0], c1[1]); RF0[3] = pkh2(c1[2], c1[3]);
        RF1[0] = pkh2(f0[0], f0[1]); RF1[1] = pkh2(f0[2], f0[3]);
        RF1[2] = pkh2(f1[0], f1[1]); RF1[3] = pkh2(f1[2], f1[3]);

        uint4 v0 = S->BV[m][j][0][lane];
        uint4 v1 = S->BV[m][j][1][lane];
        uint2 v0h = make_uint2(v0.x, v0.y), v0l = make_uint2(v0.z, v0.w);
        uint2 v1h = make_uint2(v1.x, v1.y), v1l = make_uint2(v1.z, v1.w);
        mma16816(dT0, RF0, v0h); mma16816(dT0, RF0, v0l);
        mma16816(sT0, RF0, v1h); mma16816(sT0, RF0, v1l);
        mma16816(dT1, RF1, v0h); mma16816(dT1, RF1, v0l);
        mma16816(sT1, RF1, v1h); mma16816(sT1, RF1, v1l);
    }
}

__global__ void __launch_bounds__(128, 3) visco_mma(
    const float* __restrict__ e,   const float* __restrict__ edot,
    const float* __restrict__ Eg,  const float* __restrict__ nug,
    const float* __restrict__ We1, const float* __restrict__ be1,
    const float* __restrict__ We2,
    const float* __restrict__ Wd1, const float* __restrict__ bd1,
    const float* __restrict__ Wd2,
    const float* __restrict__ WE,  const float* __restrict__ bE,
    const float* __restrict__ Wnu, const float* __restrict__ bnu,
    float* __restrict__ out)
{
    __shared__ SmemT S;

    const int tid  = threadIdx.x;
    const int wrp  = tid >> 5;
    const int lane = tid & 31;
    const int g    = lane >> 2;
    const int t4   = lane & 3;

    {   // derived per-h params: alpha, beta, gamma, 2c
        const int h = tid;
        const float* w1 = We1 + h * DIN;
        float a = be1[h], bt = 0.f, gm = 0.f;
#pragma unroll
        for (int k = 0; k < 16; ++k) { float w = w1[14 + k]; a += w * bE[k];  bt += w * WE[k]; }
#pragma unroll
        for (int k = 0; k < 16; ++k) { float w = w1[30 + k]; a += w * bnu[k]; gm += w * Wnu[k]; }
        S.ABG[0 * H + h][0] = a; S.ABG[0 * H + h][1] = bt; S.ABG[0 * H + h][2] = gm;
        S.ABG[0 * H + h][3] = 2.f * (We2[h] + We2[H + h]);
        ((float*)S.AP)[0 * H + h] = a;

        const float* w2 = Wd1 + h * DIN;
        a = bd1[h]; bt = 0.f; gm = 0.f;
#pragma unroll
        for (int k = 0; k < 16; ++k) { float w = w2[14 + k]; a += w * bE[k];  bt += w * WE[k]; }
#pragma unroll
        for (int k = 0; k < 16; ++k) { float w = w2[30 + k]; a += w * bnu[k]; gm += w * Wnu[k]; }
        S.ABG[1 * H + h][0] = a; S.ABG[1 * H + h][1] = bt; S.ABG[1 * H + h][2] = gm;
        S.ABG[1 * H + h][3] = 2.f * Wd2[h];
        ((float*)S.AP)[1 * H + h] = a;
    }
    __syncthreads();

    // GEMM1 W frags. X k-order: k0-7 = xi/−d (W cols 6..13); k8-13 = e/edot (W cols 0..5);
    // k14 = beta (E), k15 = gamma (nu).
    for (int it = tid; it < 2 * 16 * 32; it += 128) {
        int ln = it & 31, nt = (it >> 5) & 15, m = it >> 9;
        int gg = ln >> 2, tt = ln & 3, h = nt * 8 + gg;
        const float* W = (m ? Wd1 : We1) + h * DIN;
        int ks[4] = {2 * tt, 2 * tt + 1, 2 * tt + 8, 2 * tt + 9};
        uint16_t hb[4], lb[4];
#pragma unroll
        for (int i = 0; i < 4; ++i) {
            int k = ks[i];
            float v = (k < 8) ? W[6 + k]
                    : (k < 14) ? W[k - 8]
                    : (k == 14) ? S.ABG[m * H + h][1] : S.ABG[m * H + h][2];
            splits(v, hb[i], lb[i]);
        }
        S.BW[m][nt][ln] = make_uint4((uint32_t)hb[0] | ((uint32_t)hb[1] << 16),
                                     (uint32_t)hb[2] | ((uint32_t)hb[3] << 16),
                                     (uint32_t)lb[0] | ((uint32_t)lb[1] << 16),
                                     (uint32_t)lb[2] | ((uint32_t)lb[3] << 16));
    }
    // GEMM2 V frags. Output n-order: n0-7 = d/kin (W cols 6..13); n8-13 = s (W cols 0..5).
    for (int it = tid; it < 2 * 8 * 2 * 32; it += 128) {
        int ln = it & 31, nt = (it >> 5) & 1, kt = (it >> 6) & 7, m = it >> 9;
        int gg = ln >> 2, tt = ln & 3, n = nt * 8 + gg;
        const float* W = m ? Wd1 : We1;
        int hs[4] = {kt * 16 + 2 * tt, kt * 16 + 2 * tt + 1,
                     kt * 16 + 2 * tt + 8, kt * 16 + 2 * tt + 9};
        uint16_t hb[4], lb[4];
#pragma unroll
        for (int i = 0; i < 4; ++i) {
            float v = 0.f;
            if (n < 14) {
                int c = (n < 8) ? 6 + n : n - 8;
                v = S.ABG[m * H + hs[i]][3] * W[hs[i] * DIN + c];
            }
            splits(v, hb[i], lb[i]);
        }
        S.BV[m][kt][nt][ln] = make_uint4((uint32_t)hb[0] | ((uint32_t)hb[1] << 16),
                                         (uint32_t)hb[2] | ((uint32_t)hb[3] << 16),
                                         (uint32_t)lb[0] | ((uint32_t)lb[1] << 16),
                                         (uint32_t)lb[2] | ((uint32_t)lb[3] << 16));
    }
    __syncthreads();

    // ---- warp owns 32 rows; every lane owns one input row ----
    const int rb = blockIdx.x * 128 + wrp * 32;
    const int br = rb + lane;
    const float* pe = e    + (size_t)br * TD;
    const float* pd = edot + (size_t)br * TD;

    uint32_t (*stgE)[4] = S.STGE[wrp];
    uint32_t (*stgD)[4] = S.STGD[wrp];

    // loop-invariant (E, nu) fp16 pair, staged once
    {
        uint32_t u3 = pkh2(Eg[br], nug[br]);
        stgE[lane][3] = u3;
        stgD[lane][3] = u3;
    }

    // fragment-row output pointers (rows g, g+8, 16+g, 24+g)
    float* soR0 = out + (size_t)(rb + g) * TD;
    float* soR1 = soR0 + 8 * (size_t)TD;
    float* soR2 = soR0 + 16 * (size_t)TD;
    float* soR3 = soR0 + 24 * (size_t)TD;
    const size_t XOFF = (size_t)B_TOT * TD;
    float* xoR0 = out + XOFF + (size_t)(rb + g) * (T_LEN * NIV);
    float* xoR1 = xoR0 + 8 * (size_t)(T_LEN * NIV);
    float* xoR2 = xoR0 + 16 * (size_t)(T_LEN * NIV);
    float* xoR3 = xoR0 + 24 * (size_t)(T_LEN * NIV);

    // xi as register C-fragments (m-tile0: rows g,g+8; m-tile1: rows 16+g,24+g)
    float xs0[4] = {0.f, 0.f, 0.f, 0.f}, xs1[4] = {0.f, 0.f, 0.f, 0.f};

    float ce[6], cd[6];
#pragma unroll
    for (int j = 0; j < 6; ++j) { ce[j] = pe[j]; cd[j] = pd[j]; }
    __syncwarp();

    for (int t = 0; t < T_LEN; ++t) {
        // xi out (state entering step), straight from fragments
        {
            int ox = t * NIV + 2 * t4;
            *(float2*)(xoR0 + ox) = make_float2(xs0[0], xs0[1]);
            *(float2*)(xoR1 + ox) = make_float2(xs0[2], xs0[3]);
            *(float2*)(xoR2 + ox) = make_float2(xs1[0], xs1[1]);
            *(float2*)(xoR3 + ox) = make_float2(xs1[2], xs1[3]);
        }

        // stage fp16 pairs for [e(6)] / [edot(6)] (this lane's row)
        *(uint2*)&stgE[lane][0] = make_uint2(pkh2(ce[0], ce[1]), pkh2(ce[2], ce[3]));
        stgE[lane][2] = pkh2(ce[4], ce[5]);
        *(uint2*)&stgD[lane][0] = make_uint2(pkh2(cd[0], cd[1]), pkh2(cd[2], cd[3]));
        stgD[lane][2] = pkh2(cd[4], cd[5]);
        __syncwarp();

        // prefetch next step inputs
        if (t + 1 < T_LEN) {
            const int o = (t + 1) * DE;
#pragma unroll
            for (int j = 0; j < 6; j += 2) {
                float2 v1 = *(const float2*)(pe + o + j); ce[j] = v1.x; ce[j + 1] = v1.y;
                float2 v2 = *(const float2*)(pd + o + j); cd[j] = v2.x; cd[j + 1] = v2.y;
            }
        }

        // ---- E-MLP: A k0-7 from xi frags, k8-15 from stgE ----
        uint32_t aF0[4], aF1[4];
        aF0[0] = pkh2(xs0[0], xs0[1]);
        aF0[1] = pkh2(xs0[2], xs0[3]);
        aF0[2] = stgE[g][t4];
        aF0[3] = stgE[g + 8][t4];
        aF1[0] = pkh2(xs1[0], xs1[1]);
        aF1[1] = pkh2(xs1[2], xs1[3]);
        aF1[2] = stgE[16 + g][t4];
        aF1[3] = stgE[24 + g][t4];
        float dE0[4], sE0[4], dE1[4], sE1[4];
        mlp_tc(&S, 0, lane, t4, aF0, aF1, dE0, sE0, dE1, sE1);

        // ---- D-MLP: A k0-7 = -d from C-frags, k8-15 from stgD ----
        aF0[0] = pkh2(-dE0[0], -dE0[1]);
        aF0[1] = pkh2(-dE0[2], -dE0[3]);
        aF0[2] = stgD[g][t4];
        aF0[3] = stgD[g + 8][t4];
        aF1[0] = pkh2(-dE1[0], -dE1[1]);
        aF1[1] = pkh2(-dE1[2], -dE1[3]);
        aF1[2] = stgD[16 + g][t4];
        aF1[3] = stgD[24 + g][t4];
        float kn0[4], sn0[4], kn1[4], sn1[4];
        mlp_tc(&S, 1, lane, t4, aF0, aF1, kn0, sn0, kn1, sn1);

        // ---- epilogue: stress from fragments; xi frag update ----
        if (t4 < 3) {
            int oc = t * DE + 2 * t4;
            *(float2*)(soR0 + oc) = make_float2(sE0[0] - sn0[0], sE0[1] - sn0[1]);
            *(float2*)(soR1 + oc) = make_float2(sE0[2] - sn0[2], sE0[3] - sn0[3]);
            *(float2*)(soR2 + oc) = make_float2(sE1[0] - sn1[0], sE1[1] - sn1[1]);
            *(float2*)(soR3 + oc) = make_float2(sE1[2] - sn1[2], sE1[3] - sn1[3]);
        }
#pragma unroll
        for (int i = 0; i < 4; ++i) {
            xs0[i] = fmaf(kn0[i], 0.01f, xs0[i]);
            xs1[i] = fmaf(kn1[i], 0.01f, xs1[i]);
        }
        __syncwarp();   // stage arrays reused next step
    }
}

extern "C" void kernel_launch(void* const* d_in, const int* in_sizes, int n_in,
                              void* d_out, int out_size) {
    const float* e    = (const float*)d_in[0];
    const float* edot = (const float*)d_in[1];
    const float* Eg   = (const float*)d_in[2];
    const float* nug  = (const float*)d_in[3];
    const float* We1  = (const float*)d_in[4];
    const float* be1  = (const float*)d_in[5];
    const float* We2  = (const float*)d_in[6];
    const float* Wd1  = (const float*)d_in[8];
    const float* bd1  = (const float*)d_in[9];
    const float* Wd2  = (const float*)d_in[10];
    const float* WE   = (const float*)d_in[12];
    const float* bE   = (const float*)d_in[13];
    const float* Wnu  = (const float*)d_in[14];
    const float* bnu  = (const float*)d_in[15];
    float* out = (float*)d_out;

    visco_mma<<<NCTA, 128>>>(e, edot, Eg, nug, We1, be1, We2,
                             Wd1, bd1, Wd2, WE, bE, Wnu, bnu, out);
}